// round 5
// baseline (speedup 1.0000x reference)
#include <cuda_runtime.h>
#include <cuda_fp16.h>
#include <math.h>
#include <stdint.h>

// ---------------- problem constants ----------------
#define BSZ   2
#define LSEQ  512
#define DMODEL 1024
#define DINNER 2048
#define DSTATE 64
#define KCONV 4
#define MROWS (BSZ*LSEQ)     // 1024
#define NXP   129
#define KCH   8
#define KSZ   (DINNER/KCH)
#define OUT_ELEMS (MROWS*DMODEL)

// ---------------- device scratch ----------------
__device__ __align__(16) float g_xz  [MROWS * 2 * DINNER];
__device__ __align__(16) float g_xs  [MROWS * DINNER];
__device__ __align__(16) float g_xpp [KCH * MROWS * NXP];
__device__ __align__(16) float g_Bm  [MROWS * DSTATE];
__device__ __align__(16) float g_Cm  [MROWS * DSTATE];
__device__ __align__(16) float g_dtr [MROWS];
// fp16 hi/lo operand buffers
__device__ __align__(16) __half g_xh [MROWS * DMODEL];
__device__ __align__(16) __half g_xl [MROWS * DMODEL];
__device__ __align__(16) __half g_w1h[2 * DINNER * DMODEL];   // W1^T [4096][1024]
__device__ __align__(16) __half g_w1l[2 * DINNER * DMODEL];
__device__ __align__(16) __half g_w3h[DMODEL * DINNER];        // W3^T [1024][2048]
__device__ __align__(16) __half g_w3l[DMODEL * DINNER];
__device__ __align__(16) __half g_yh [MROWS * DINNER];
__device__ __align__(16) __half g_yl [MROWS * DINNER];

// ================= helpers =================
__device__ __forceinline__ uint32_t smem_u32(const void* p) {
    uint32_t a;
    asm("{ .reg .u64 t; cvta.to.shared.u64 t, %1; cvt.u32.u64 %0, t; }" : "=r"(a) : "l"(p));
    return a;
}
__device__ __forceinline__ void cp16(uint32_t d, const void* s) {
    asm volatile("cp.async.cg.shared.global [%0], [%1], 16;" :: "r"(d), "l"(s));
}
#define CP_COMMIT() asm volatile("cp.async.commit_group;" ::: "memory")
#define CP_WAIT1()  asm volatile("cp.async.wait_group 1;" ::: "memory")

__device__ __forceinline__ void mma16816(float4& d,
    uint32_t a0, uint32_t a1, uint32_t a2, uint32_t a3,
    uint32_t b0, uint32_t b1)
{
    asm("mma.sync.aligned.m16n8k16.row.col.f32.f16.f16.f32 "
        "{%0,%1,%2,%3}, {%4,%5,%6,%7}, {%8,%9}, {%0,%1,%2,%3};"
        : "+f"(d.x), "+f"(d.y), "+f"(d.z), "+f"(d.w)
        : "r"(a0), "r"(a1), "r"(a2), "r"(a3), "r"(b0), "r"(b1));
}

// ================= fp16 hi/lo GEMM =================
// C[M,N] = A[M,K] @ B^T where A given as (Ah,Al) [M][K] and B^T as (Bh,Bl) [N][K].
// D = Ah*Bh + Ah*Bl + Al*Bh (fp32 accum). ksplit>1 -> atomicAdd into zeroed C.
#define BM 128
#define BN 128
#define BK 32
#define PITCH 40               // halfs per smem row (32 + 8 pad) = 80B
#define TSTG (128*PITCH)       // halfs per tile buffer
#define STG  (4*TSTG)          // halfs per stage (Ah,Al,Bh,Bl)
#define GSMEM (2*STG*2)        // bytes, double buffered = 81920

__global__ __launch_bounds__(256, 2) void gemm_hl(
    const __half* __restrict__ Ah, const __half* __restrict__ Al,
    const __half* __restrict__ Bh, const __half* __restrict__ Bl,
    float* __restrict__ C, int M, int N, int K, int ksplit)
{
    extern __shared__ __half sm[];
    const uint32_t sbase = smem_u32(sm);
    const int tid  = threadIdx.x;
    const int lane = tid & 31, warp = tid >> 5;
    const int gid  = lane >> 2, tig = lane & 3;
    const int wm   = warp >> 2, wn = warp & 3;
    const int m0 = blockIdx.y * BM, n0 = blockIdx.x * BN;
    const int kchunk = K / ksplit;
    const int kbeg   = blockIdx.z * kchunk;
    const int NCH    = kchunk / BK;

    // staging: 4 tiles (Ah,Al,Bh,Bl), 64 threads per tile, 8 x 16B chunks each
    const int tile = tid >> 6;
    const int lt   = tid & 63;
    const __half* srcb = (tile == 0) ? Ah : (tile == 1) ? Al : (tile == 2) ? Bh : Bl;
    const int rowoff   = (tile < 2) ? m0 : n0;

    auto issue = [&](int c) {
        const int k0 = kbeg + c * BK;
        const uint32_t sb = sbase + ((c & 1) * STG + tile * TSTG) * 2;
#pragma unroll
        for (int j = 0; j < 8; ++j) {
            int idx = lt * 8 + j;
            int row = idx >> 2, ch = idx & 3;
            cp16(sb + (uint32_t)(row * PITCH + ch * 8) * 2,
                 srcb + (size_t)(rowoff + row) * K + k0 + ch * 8);
        }
    };

    float4 acc[4][4];
#pragma unroll
    for (int i = 0; i < 4; i++)
#pragma unroll
        for (int j = 0; j < 4; j++) acc[i][j] = make_float4(0.f, 0.f, 0.f, 0.f);

    issue(0); CP_COMMIT();
    issue(1); CP_COMMIT();

    for (int c = 0; c < NCH; ++c) {
        CP_WAIT1();
        __syncthreads();

        const __half* base = sm + (c & 1) * STG;
        const __half* sAh = base;
        const __half* sAl = base + TSTG;
        const __half* sBh = base + 2 * TSTG;
        const __half* sBl = base + 3 * TSTG;

#pragma unroll
        for (int ks = 0; ks < 2; ++ks) {
            const int kb = ks * 16 + tig * 2;
            uint32_t bh[4][2], bl[4][2];
#pragma unroll
            for (int nf = 0; nf < 4; ++nf) {
                const __half* q  = sBh + (wn * 32 + nf * 8 + gid) * PITCH + kb;
                const __half* ql = sBl + (wn * 32 + nf * 8 + gid) * PITCH + kb;
                bh[nf][0] = *(const uint32_t*)q;
                bh[nf][1] = *(const uint32_t*)(q + 8);
                bl[nf][0] = *(const uint32_t*)ql;
                bl[nf][1] = *(const uint32_t*)(ql + 8);
            }
#pragma unroll
            for (int mf = 0; mf < 4; ++mf) {
                const __half* qa = sAh + (wm * 64 + mf * 16 + gid) * PITCH + kb;
                const __half* qb = sAl + (wm * 64 + mf * 16 + gid) * PITCH + kb;
                uint32_t ah0 = *(const uint32_t*)qa;
                uint32_t ah1 = *(const uint32_t*)(qa + 8 * PITCH);
                uint32_t ah2 = *(const uint32_t*)(qa + 8);
                uint32_t ah3 = *(const uint32_t*)(qa + 8 * PITCH + 8);
                uint32_t al0 = *(const uint32_t*)qb;
                uint32_t al1 = *(const uint32_t*)(qb + 8 * PITCH);
                uint32_t al2 = *(const uint32_t*)(qb + 8);
                uint32_t al3 = *(const uint32_t*)(qb + 8 * PITCH + 8);
                // three passes, each pass has 4 independent accumulators
#pragma unroll
                for (int nf = 0; nf < 4; ++nf)
                    mma16816(acc[mf][nf], ah0, ah1, ah2, ah3, bh[nf][0], bh[nf][1]);
#pragma unroll
                for (int nf = 0; nf < 4; ++nf)
                    mma16816(acc[mf][nf], ah0, ah1, ah2, ah3, bl[nf][0], bl[nf][1]);
#pragma unroll
                for (int nf = 0; nf < 4; ++nf)
                    mma16816(acc[mf][nf], al0, al1, al2, al3, bh[nf][0], bh[nf][1]);
            }
        }
        __syncthreads();
        if (c + 2 < NCH) issue(c + 2);
        CP_COMMIT();
    }

#pragma unroll
    for (int mf = 0; mf < 4; ++mf)
#pragma unroll
        for (int nf = 0; nf < 4; ++nf) {
            int r  = m0 + wm * 64 + mf * 16 + gid;
            int cc = n0 + wn * 32 + nf * 8 + tig * 2;
            float4 v = acc[mf][nf];
            if (ksplit == 1) {
                *(float2*)(C + (size_t)r * N + cc)       = make_float2(v.x, v.y);
                *(float2*)(C + (size_t)(r + 8) * N + cc) = make_float2(v.z, v.w);
            } else {
                atomicAdd(C + (size_t)r * N + cc,           v.x);
                atomicAdd(C + (size_t)r * N + cc + 1,       v.y);
                atomicAdd(C + (size_t)(r + 8) * N + cc,     v.z);
                atomicAdd(C + (size_t)(r + 8) * N + cc + 1, v.w);
            }
        }
}

// ---------------- pre-pass: x -> fp16 hi/lo ----------------
__global__ void cvt_x_kernel(const float* __restrict__ x)
{
    int i = (blockIdx.x * 256 + threadIdx.x) * 4;
    float4 v = *(const float4*)(x + i);
    __half h0 = __float2half_rn(v.x), h1 = __float2half_rn(v.y);
    __half h2 = __float2half_rn(v.z), h3 = __float2half_rn(v.w);
    __half l0 = __float2half_rn(v.x - __half2float(h0));
    __half l1 = __float2half_rn(v.y - __half2float(h1));
    __half l2 = __float2half_rn(v.z - __half2float(h2));
    __half l3 = __float2half_rn(v.w - __half2float(h3));
    __half hh[4] = {h0, h1, h2, h3};
    __half ll[4] = {l0, l1, l2, l3};
    *(uint2*)(g_xh + i) = *(uint2*)hh;
    *(uint2*)(g_xl + i) = *(uint2*)ll;
}

// ---------------- pre-pass: W [K][N] -> W^T hi/lo [N][K] fp16 ----------------
__global__ void tconv_kernel(const float* __restrict__ W,
                             __half* __restrict__ Th, __half* __restrict__ Tl,
                             int K, int N)
{
    __shared__ float t[32][33];
    const int n0 = blockIdx.x * 32, k0 = blockIdx.y * 32;
    const int tx = threadIdx.x, ty = threadIdx.y;  // 32 x 8
#pragma unroll
    for (int i = 0; i < 4; ++i)
        t[ty + i * 8][tx] = W[(size_t)(k0 + ty + i * 8) * N + n0 + tx];
    __syncthreads();
#pragma unroll
    for (int i = 0; i < 4; ++i) {
        int r = ty + i * 8;
        float v = t[tx][r];
        __half h = __float2half_rn(v);
        __half l = __float2half_rn(v - __half2float(h));
        Th[(size_t)(n0 + r) * K + k0 + tx] = h;
        Tl[(size_t)(n0 + r) * K + k0 + tx] = l;
    }
}

// ---------------- depthwise causal conv (K=4) + bias + SiLU ----------------
__global__ void conv_silu_kernel(const float* __restrict__ conv_w,
                                 const float* __restrict__ conv_b)
{
    const int m = blockIdx.x;
    const int b = m / LSEQ;
    const int l = m % LSEQ;
    for (int c = threadIdx.x; c < DINNER; c += blockDim.x) {
        float s = conv_b[c];
#pragma unroll
        for (int k = 0; k < KCONV; k++) {
            int ls = l - (KCONV - 1) + k;
            if (ls >= 0)
                s += g_xz[(size_t)(b * LSEQ + ls) * (2 * DINNER) + c] * conv_w[c * KCONV + k];
        }
        float sil = s / (1.f + __expf(-s));
        g_xs[(size_t)m * DINNER + c] = sil;
    }
}

// ---------------- x-proj split-K partials ----------------
__global__ __launch_bounds__(160) void xp_partial_kernel(const float* __restrict__ W)
{
    __shared__ float s[16][KSZ];
    const int m0 = blockIdx.x * 16;
    const int k0 = blockIdx.y * KSZ;
    const int tid = threadIdx.x;

    for (int idx = tid; idx < 16 * KSZ; idx += blockDim.x) {
        int r = idx / KSZ, k = idx % KSZ;
        s[r][k] = g_xs[(size_t)(m0 + r) * DINNER + k0 + k];
    }
    __syncthreads();

    if (tid < NXP) {
        float acc[16];
#pragma unroll
        for (int r = 0; r < 16; r++) acc[r] = 0.f;
        for (int k = 0; k < KSZ; k++) {
            float w = W[(size_t)(k0 + k) * NXP + tid];
#pragma unroll
            for (int r = 0; r < 16; r++) acc[r] += s[r][k] * w;
        }
#pragma unroll
        for (int r = 0; r < 16; r++)
            g_xpp[(size_t)(blockIdx.y * MROWS + m0 + r) * NXP + tid] = acc[r];
    }
}

__global__ __launch_bounds__(160) void xp_reduce_kernel()
{
    const int m = blockIdx.x;
    const int n = threadIdx.x;
    if (n >= NXP) return;
    float sum = 0.f;
#pragma unroll
    for (int kc = 0; kc < KCH; kc++)
        sum += g_xpp[(size_t)(kc * MROWS + m) * NXP + n];
    if (n < DSTATE)            g_Bm[m * DSTATE + n] = sum;
    else if (n < 2 * DSTATE)   g_Cm[m * DSTATE + (n - DSTATE)] = sum;
    else                       g_dtr[m] = sum;
}

// ---------------- selective scan (softplus fused, fp16 hi/lo y output) -----
__global__ __launch_bounds__(256) void scan_kernel(
    const float* __restrict__ A_log, const float* __restrict__ Dp,
    const float* __restrict__ dt_w, const float* __restrict__ dt_b,
    float* __restrict__ state_out)
{
    __shared__ float sB[2][64], sC[2][64], sdt[2][8], sxs[2][8], sz[2][8];

    const int tid  = threadIdx.x;
    const int warp = tid >> 5;
    const int lane = tid & 31;
    const int b  = blockIdx.x >> 8;
    const int d0 = (blockIdx.x & 255) * 8;
    const int d  = d0 + warp;

    const float a0 = -__expf(A_log[d * DSTATE + lane]);
    const float a1 = -__expf(A_log[d * DSTATE + lane + 32]);
    const float Dd = Dp[d];

    float dw = 0.f, db = 0.f;
    if (tid >= 128 && tid < 136) {
        dw = dt_w[d0 + tid - 128];
        db = dt_b[d0 + tid - 128];
    }

    auto stage = [&](int t, int p) {
        const int m = b * LSEQ + t;
        if (tid < 64)        sB[p][tid]      = g_Bm[m * DSTATE + tid];
        else if (tid < 128)  sC[p][tid - 64] = g_Cm[m * DSTATE + tid - 64];
        else if (tid < 136) {
            float v = g_dtr[m] * dw + db;
            sdt[p][tid - 128] = (v > 20.f) ? v : log1pf(__expf(v));
        }
        else if (tid < 144)  sxs[p][tid - 136] = g_xs[(size_t)m * DINNER + d0 + tid - 136];
        else if (tid < 152)  sz[p][tid - 144]  = g_xz[(size_t)m * (2 * DINNER) + DINNER + d0 + tid - 144];
    };

    stage(0, 0);
    float s0 = 0.f, s1 = 0.f;
    int p = 0;
    for (int t = 0; t < LSEQ; ++t) {
        __syncthreads();
        if (t + 1 < LSEQ) stage(t + 1, p ^ 1);

        const float dtv = sdt[p][warp];
        const float xv  = sxs[p][warp];
        const float zv  = sz[p][warp];
        const float b0  = sB[p][lane];
        const float b1  = sB[p][lane + 32];
        const float c0  = sC[p][lane];
        const float c1  = sC[p][lane + 32];

        const float dx = dtv * xv;
        s0 = __expf(dtv * a0) * s0 + dx * b0;
        s1 = __expf(dtv * a1) * s1 + dx * b1;

        float acc = s0 * c0 + s1 * c1;
#pragma unroll
        for (int o = 16; o; o >>= 1) acc += __shfl_xor_sync(0xffffffffu, acc, o);

        if (lane == 0) {
            const int m = b * LSEQ + t;
            float y = acc + Dd * xv;
            float sg = zv / (1.f + __expf(-zv));
            float yv = y * sg;
            __half hy = __float2half_rn(yv);
            __half ly = __float2half_rn(yv - __half2float(hy));
            g_yh[(size_t)m * DINNER + d] = hy;
            g_yl[(size_t)m * DINNER + d] = ly;
        }
        p ^= 1;
    }
    state_out[(size_t)(b * DINNER + d) * DSTATE + lane]      = s0;
    state_out[(size_t)(b * DINNER + d) * DSTATE + lane + 32] = s1;
}

// ---------------- launch ----------------
extern "C" void kernel_launch(void* const* d_in, const int* in_sizes, int n_in,
                              void* d_out, int out_size)
{
    const float* x          = (const float*)d_in[0];
    const float* in_proj_w  = (const float*)d_in[1];
    const float* conv_w     = (const float*)d_in[2];
    const float* conv_b     = (const float*)d_in[3];
    const float* x_proj_w   = (const float*)d_in[4];
    const float* dt_w       = (const float*)d_in[5];
    const float* dt_b       = (const float*)d_in[6];
    const float* A_log      = (const float*)d_in[7];
    const float* Dp         = (const float*)d_in[8];
    const float* out_proj_w = (const float*)d_in[9];
    float* out = (float*)d_out;

    void* p;
    cudaGetSymbolAddress(&p, g_xz);  float*  p_xz  = (float*)p;
    cudaGetSymbolAddress(&p, g_xh);  __half* p_xh  = (__half*)p;
    cudaGetSymbolAddress(&p, g_xl);  __half* p_xl  = (__half*)p;
    cudaGetSymbolAddress(&p, g_w1h); __half* p_w1h = (__half*)p;
    cudaGetSymbolAddress(&p, g_w1l); __half* p_w1l = (__half*)p;
    cudaGetSymbolAddress(&p, g_w3h); __half* p_w3h = (__half*)p;
    cudaGetSymbolAddress(&p, g_w3l); __half* p_w3l = (__half*)p;
    cudaGetSymbolAddress(&p, g_yh);  __half* p_yh  = (__half*)p;
    cudaGetSymbolAddress(&p, g_yl);  __half* p_yl  = (__half*)p;

    cudaFuncSetAttribute(gemm_hl, cudaFuncAttributeMaxDynamicSharedMemorySize, GSMEM);

    // zero C for split-K GEMM3
    cudaMemsetAsync(out, 0, (size_t)OUT_ELEMS * sizeof(float));

    // 0) pre-passes: convert x, transpose+convert weights
    cvt_x_kernel<<<(MROWS * DMODEL) / 1024, 256>>>(x);
    tconv_kernel<<<dim3(2 * DINNER / 32, DMODEL / 32), dim3(32, 8)>>>(
        in_proj_w, p_w1h, p_w1l, DMODEL, 2 * DINNER);
    tconv_kernel<<<dim3(DMODEL / 32, DINNER / 32), dim3(32, 8)>>>(
        out_proj_w, p_w3h, p_w3l, DINNER, DMODEL);

    // 1) xz = x @ in_proj_w  (M=1024, N=4096, K=1024)
    gemm_hl<<<dim3(2 * DINNER / BN, MROWS / BM, 1), 256, GSMEM>>>(
        p_xh, p_xl, p_w1h, p_w1l, p_xz, MROWS, 2 * DINNER, DMODEL, 1);

    // 2) depthwise causal conv + SiLU
    conv_silu_kernel<<<MROWS, 256>>>(conv_w, conv_b);

    // 3) xp = xs @ x_proj_w (split-K fp32) -> Bm, Cm, dt_raw
    xp_partial_kernel<<<dim3(MROWS / 16, KCH), 160>>>(x_proj_w);
    xp_reduce_kernel<<<MROWS, 160>>>();

    // 4) selective scan (softplus fused) -> yh/yl, final state -> d_out tail
    scan_kernel<<<512, 256>>>(A_log, Dp, dt_w, dt_b, out + OUT_ELEMS);

    // 5) out = y @ out_proj_w (M=1024, N=1024, K=2048), split-K=4
    gemm_hl<<<dim3(DMODEL / BN, MROWS / BM, 4), 256, GSMEM>>>(
        p_yh, p_yl, p_w3h, p_w3l, out, MROWS, DMODEL, DINNER, 4);
}

// round 6
// speedup vs baseline: 1.3726x; 1.3726x over previous
#include <cuda_runtime.h>
#include <cuda_fp16.h>
#include <math.h>
#include <stdint.h>

// ---------------- problem constants ----------------
#define BSZ   2
#define LSEQ  512
#define DMODEL 1024
#define DINNER 2048
#define DSTATE 64
#define KCONV 4
#define MROWS (BSZ*LSEQ)     // 1024
#define NXP   129
#define KCH   8
#define KSZ   (DINNER/KCH)
#define OUT_ELEMS (MROWS*DMODEL)

// ---------------- device scratch ----------------
__device__ __align__(16) float g_xz  [MROWS * 2 * DINNER];
__device__ __align__(16) float g_xs  [MROWS * DINNER];
__device__ __align__(16) float g_xpp [KCH * MROWS * NXP];
__device__ __align__(16) float g_Bm  [MROWS * DSTATE];
__device__ __align__(16) float g_Cm  [MROWS * DSTATE];
__device__ __align__(16) float g_dtr [MROWS];
__device__ __align__(16) __half g_xh [MROWS * DMODEL];
__device__ __align__(16) __half g_xl [MROWS * DMODEL];
__device__ __align__(16) __half g_w1h[2 * DINNER * DMODEL];
__device__ __align__(16) __half g_w1l[2 * DINNER * DMODEL];
__device__ __align__(16) __half g_w3h[DMODEL * DINNER];
__device__ __align__(16) __half g_w3l[DMODEL * DINNER];
__device__ __align__(16) __half g_yh [MROWS * DINNER];
__device__ __align__(16) __half g_yl [MROWS * DINNER];

// ================= helpers =================
__device__ __forceinline__ uint32_t smem_u32(const void* p) {
    uint32_t a;
    asm("{ .reg .u64 t; cvta.to.shared.u64 t, %1; cvt.u32.u64 %0, t; }" : "=r"(a) : "l"(p));
    return a;
}
__device__ __forceinline__ void cp16(uint32_t d, const void* s) {
    asm volatile("cp.async.cg.shared.global [%0], [%1], 16;" :: "r"(d), "l"(s));
}
#define CP_COMMIT() asm volatile("cp.async.commit_group;" ::: "memory")
#define CP_WAIT1()  asm volatile("cp.async.wait_group 1;" ::: "memory")

__device__ __forceinline__ void ldsm4(uint32_t& r0, uint32_t& r1, uint32_t& r2, uint32_t& r3, uint32_t a) {
    asm volatile("ldmatrix.sync.aligned.m8n8.x4.shared.b16 {%0,%1,%2,%3}, [%4];"
        : "=r"(r0), "=r"(r1), "=r"(r2), "=r"(r3) : "r"(a));
}

__device__ __forceinline__ void mma16816(float4& d,
    uint32_t a0, uint32_t a1, uint32_t a2, uint32_t a3,
    uint32_t b0, uint32_t b1)
{
    asm("mma.sync.aligned.m16n8k16.row.col.f32.f16.f16.f32 "
        "{%0,%1,%2,%3}, {%4,%5,%6,%7}, {%8,%9}, {%0,%1,%2,%3};"
        : "+f"(d.x), "+f"(d.y), "+f"(d.z), "+f"(d.w)
        : "r"(a0), "r"(a1), "r"(a2), "r"(a3), "r"(b0), "r"(b1));
}

// ================= fp16 hi/lo GEMM (ldmatrix operand path) =================
// C[M,N] = A[M,K] @ B^T with A as (Ah,Al)[M][K], B^T as (Bh,Bl)[N][K].
// D = Ah*Bh + Ah*Bl + Al*Bh, fp32 accum. ksplit>1 -> atomicAdd into zeroed C.
#define BM 128
#define BN 128
#define BK 32
#define PITCH 40               // halfs per smem row (32 + 8 pad) = 80B
#define TSTG (128*PITCH)       // halfs per tile buffer
#define STG  (4*TSTG)          // halfs per stage (Ah,Al,Bh,Bl)
#define GSMEM (2*STG*2)        // bytes, double buffered = 81920

__global__ __launch_bounds__(256, 2) void gemm_hl(
    const __half* __restrict__ Ah, const __half* __restrict__ Al,
    const __half* __restrict__ Bh, const __half* __restrict__ Bl,
    float* __restrict__ C, int M, int N, int K, int ksplit)
{
    extern __shared__ __half sm[];
    const uint32_t sbase = smem_u32(sm);
    const int tid  = threadIdx.x;
    const int lane = tid & 31, warp = tid >> 5;
    const int gid  = lane >> 2, tig = lane & 3;
    const int wm   = warp >> 2, wn = warp & 3;
    const int m0 = blockIdx.y * BM, n0 = blockIdx.x * BN;
    const int kchunk = K / ksplit;
    const int kbeg   = blockIdx.z * kchunk;
    const int NCH    = kchunk / BK;

    // ---- staging: 4 tiles (Ah,Al,Bh,Bl), 64 threads/tile, 8 x 16B each ----
    const int tile = tid >> 6;
    const int lt   = tid & 63;
    const __half* srcb = (tile == 0) ? Ah : (tile == 1) ? Al : (tile == 2) ? Bh : Bl;
    const int rowoff   = (tile < 2) ? m0 : n0;

    auto issue = [&](int c) {
        const int k0 = kbeg + c * BK;
        const uint32_t sb = sbase + ((c & 1) * STG + tile * TSTG) * 2;
#pragma unroll
        for (int j = 0; j < 8; ++j) {
            int idx = lt * 8 + j;
            int row = idx >> 2, ch = idx & 3;
            cp16(sb + (uint32_t)(row * PITCH + ch * 8) * 2,
                 srcb + (size_t)(rowoff + row) * K + k0 + ch * 8);
        }
    };

    // ---- ldmatrix lane address offsets (bytes within a tile buffer) ----
    const int matid = lane >> 3, mrow = lane & 7;
    // A x4: mats {rows0-7,k0-7},{rows8-15,k0-7},{rows0-7,k8-15},{rows8-15,k8-15}
    const uint32_t aOff = (uint32_t)((wm * 64 + (matid & 1) * 8 + mrow) * PITCH
                                     + (matid >> 1) * 8) * 2;
    // B x4: mats {n+0..7,k0-7},{n+0..7,k8-15},{n+8..15,k0-7},{n+8..15,k8-15}
    const uint32_t bOff = (uint32_t)((wn * 32 + (matid >> 1) * 8 + mrow) * PITCH
                                     + (matid & 1) * 8) * 2;

    float4 acc[4][4];
#pragma unroll
    for (int i = 0; i < 4; i++)
#pragma unroll
        for (int j = 0; j < 4; j++) acc[i][j] = make_float4(0.f, 0.f, 0.f, 0.f);

    issue(0); CP_COMMIT();
    issue(1); CP_COMMIT();

    for (int c = 0; c < NCH; ++c) {
        CP_WAIT1();
        __syncthreads();

        const uint32_t buf = sbase + (uint32_t)(c & 1) * STG * 2;
        const uint32_t tAh = buf;
        const uint32_t tAl = buf + TSTG * 2;
        const uint32_t tBh = buf + 2 * TSTG * 2;
        const uint32_t tBl = buf + 3 * TSTG * 2;

#pragma unroll
        for (int ks = 0; ks < 2; ++ks) {
            const uint32_t ko = ks * 32;   // 16 halfs
            uint32_t bh[4][2], bl[4][2];
            // each x4 covers 2 n8-fragments (b0,b1 per fragment)
            ldsm4(bh[0][0], bh[0][1], bh[1][0], bh[1][1], tBh + bOff + ko);
            ldsm4(bh[2][0], bh[2][1], bh[3][0], bh[3][1], tBh + bOff + 16 * PITCH * 2 + ko);
            ldsm4(bl[0][0], bl[0][1], bl[1][0], bl[1][1], tBl + bOff + ko);
            ldsm4(bl[2][0], bl[2][1], bl[3][0], bl[3][1], tBl + bOff + 16 * PITCH * 2 + ko);
#pragma unroll
            for (int mf = 0; mf < 4; ++mf) {
                const uint32_t amo = (uint32_t)(mf * 16 * PITCH) * 2 + ko;
                uint32_t ah0, ah1, ah2, ah3, al0, al1, al2, al3;
                ldsm4(ah0, ah1, ah2, ah3, tAh + aOff + amo);
                ldsm4(al0, al1, al2, al3, tAl + aOff + amo);
#pragma unroll
                for (int nf = 0; nf < 4; ++nf)
                    mma16816(acc[mf][nf], ah0, ah1, ah2, ah3, bh[nf][0], bh[nf][1]);
#pragma unroll
                for (int nf = 0; nf < 4; ++nf)
                    mma16816(acc[mf][nf], ah0, ah1, ah2, ah3, bl[nf][0], bl[nf][1]);
#pragma unroll
                for (int nf = 0; nf < 4; ++nf)
                    mma16816(acc[mf][nf], al0, al1, al2, al3, bh[nf][0], bh[nf][1]);
            }
        }
        __syncthreads();
        if (c + 2 < NCH) issue(c + 2);
        CP_COMMIT();
    }

#pragma unroll
    for (int mf = 0; mf < 4; ++mf)
#pragma unroll
        for (int nf = 0; nf < 4; ++nf) {
            int r  = m0 + wm * 64 + mf * 16 + gid;
            int cc = n0 + wn * 32 + nf * 8 + tig * 2;
            float4 v = acc[mf][nf];
            if (ksplit == 1) {
                *(float2*)(C + (size_t)r * N + cc)       = make_float2(v.x, v.y);
                *(float2*)(C + (size_t)(r + 8) * N + cc) = make_float2(v.z, v.w);
            } else {
                atomicAdd(C + (size_t)r * N + cc,           v.x);
                atomicAdd(C + (size_t)r * N + cc + 1,       v.y);
                atomicAdd(C + (size_t)(r + 8) * N + cc,     v.z);
                atomicAdd(C + (size_t)(r + 8) * N + cc + 1, v.w);
            }
        }
}

// ---------------- pre-pass: x -> fp16 hi/lo ----------------
__global__ void cvt_x_kernel(const float* __restrict__ x)
{
    int i = (blockIdx.x * 256 + threadIdx.x) * 4;
    float4 v = *(const float4*)(x + i);
    __half h0 = __float2half_rn(v.x), h1 = __float2half_rn(v.y);
    __half h2 = __float2half_rn(v.z), h3 = __float2half_rn(v.w);
    __half l0 = __float2half_rn(v.x - __half2float(h0));
    __half l1 = __float2half_rn(v.y - __half2float(h1));
    __half l2 = __float2half_rn(v.z - __half2float(h2));
    __half l3 = __float2half_rn(v.w - __half2float(h3));
    __half hh[4] = {h0, h1, h2, h3};
    __half ll[4] = {l0, l1, l2, l3};
    *(uint2*)(g_xh + i) = *(uint2*)hh;
    *(uint2*)(g_xl + i) = *(uint2*)ll;
}

// ---------------- pre-pass: W [K][N] -> W^T hi/lo [N][K] fp16 ----------------
__global__ void tconv_kernel(const float* __restrict__ W,
                             __half* __restrict__ Th, __half* __restrict__ Tl,
                             int K, int N)
{
    __shared__ float t[32][33];
    const int n0 = blockIdx.x * 32, k0 = blockIdx.y * 32;
    const int tx = threadIdx.x, ty = threadIdx.y;
#pragma unroll
    for (int i = 0; i < 4; ++i)
        t[ty + i * 8][tx] = W[(size_t)(k0 + ty + i * 8) * N + n0 + tx];
    __syncthreads();
#pragma unroll
    for (int i = 0; i < 4; ++i) {
        int r = ty + i * 8;
        float v = t[tx][r];
        __half h = __float2half_rn(v);
        __half l = __float2half_rn(v - __half2float(h));
        Th[(size_t)(n0 + r) * K + k0 + tx] = h;
        Tl[(size_t)(n0 + r) * K + k0 + tx] = l;
    }
}

// ---------------- depthwise causal conv (K=4) + bias + SiLU ----------------
__global__ void conv_silu_kernel(const float* __restrict__ conv_w,
                                 const float* __restrict__ conv_b)
{
    const int m = blockIdx.x;
    const int b = m / LSEQ;
    const int l = m % LSEQ;
    for (int c = threadIdx.x; c < DINNER; c += blockDim.x) {
        float s = conv_b[c];
#pragma unroll
        for (int k = 0; k < KCONV; k++) {
            int ls = l - (KCONV - 1) + k;
            if (ls >= 0)
                s += g_xz[(size_t)(b * LSEQ + ls) * (2 * DINNER) + c] * conv_w[c * KCONV + k];
        }
        float sil = s / (1.f + __expf(-s));
        g_xs[(size_t)m * DINNER + c] = sil;
    }
}

// ---------------- x-proj split-K partials ----------------
__global__ __launch_bounds__(160) void xp_partial_kernel(const float* __restrict__ W)
{
    __shared__ float s[16][KSZ];
    const int m0 = blockIdx.x * 16;
    const int k0 = blockIdx.y * KSZ;
    const int tid = threadIdx.x;

    for (int idx = tid; idx < 16 * KSZ; idx += blockDim.x) {
        int r = idx / KSZ, k = idx % KSZ;
        s[r][k] = g_xs[(size_t)(m0 + r) * DINNER + k0 + k];
    }
    __syncthreads();

    if (tid < NXP) {
        float acc[16];
#pragma unroll
        for (int r = 0; r < 16; r++) acc[r] = 0.f;
        for (int k = 0; k < KSZ; k++) {
            float w = W[(size_t)(k0 + k) * NXP + tid];
#pragma unroll
            for (int r = 0; r < 16; r++) acc[r] += s[r][k] * w;
        }
#pragma unroll
        for (int r = 0; r < 16; r++)
            g_xpp[(size_t)(blockIdx.y * MROWS + m0 + r) * NXP + tid] = acc[r];
    }
}

__global__ __launch_bounds__(160) void xp_reduce_kernel()
{
    const int m = blockIdx.x;
    const int n = threadIdx.x;
    if (n >= NXP) return;
    float sum = 0.f;
#pragma unroll
    for (int kc = 0; kc < KCH; kc++)
        sum += g_xpp[(size_t)(kc * MROWS + m) * NXP + n];
    if (n < DSTATE)            g_Bm[m * DSTATE + n] = sum;
    else if (n < 2 * DSTATE)   g_Cm[m * DSTATE + (n - DSTATE)] = sum;
    else                       g_dtr[m] = sum;
}

// ---------------- selective scan: warp-autonomous, barrier-free -------------
// warp owns (b, d); lane holds states n = 2*lane, 2*lane+1 (float2 loads).
__global__ __launch_bounds__(256) void scan_kernel(
    const float* __restrict__ A_log, const float* __restrict__ Dp,
    const float* __restrict__ dt_w, const float* __restrict__ dt_b,
    float* __restrict__ state_out)
{
    const int warp = threadIdx.x >> 5;
    const int lane = threadIdx.x & 31;
    const int wg = blockIdx.x * 8 + warp;     // 0..4095
    const int b = wg >> 11;
    const int d = wg & (DINNER - 1);

    const float a0 = -__expf(A_log[d * DSTATE + 2 * lane]);
    const float a1 = -__expf(A_log[d * DSTATE + 2 * lane + 1]);
    const float Dd = Dp[d];
    const float dw = dt_w[d], db = dt_b[d];

    const float2* B2 = (const float2*)g_Bm;
    const float2* C2 = (const float2*)g_Cm;
    const int mbase = b * LSEQ;
    const int mlast = mbase + LSEQ - 1;

    // depth-1 register prefetch
    int m = mbase;
    float2 Bn = B2[(size_t)m * 32 + lane];
    float2 Cn = C2[(size_t)m * 32 + lane];
    float dtrn = g_dtr[m];
    float xsn  = g_xs[(size_t)m * DINNER + d];
    float zn   = g_xz[(size_t)m * (2 * DINNER) + DINNER + d];

    float s0 = 0.f, s1 = 0.f;
    for (int t = 0; t < LSEQ; ++t) {
        const float2 Bc = Bn, Cc = Cn;
        const float dtrc = dtrn, xsc = xsn, zc = zn;

        const int mn = (m < mlast) ? m + 1 : mlast;
        Bn   = B2[(size_t)mn * 32 + lane];
        Cn   = C2[(size_t)mn * 32 + lane];
        dtrn = g_dtr[mn];
        xsn  = g_xs[(size_t)mn * DINNER + d];
        zn   = g_xz[(size_t)mn * (2 * DINNER) + DINNER + d];

        const float v = dtrc * dw + db;
        const float dtv = (v > 20.f) ? v : __logf(1.f + __expf(v));
        const float dx = dtv * xsc;
        s0 = __expf(dtv * a0) * s0 + dx * Bc.x;
        s1 = __expf(dtv * a1) * s1 + dx * Bc.y;

        float acc = s0 * Cc.x + s1 * Cc.y;
#pragma unroll
        for (int o = 16; o; o >>= 1) acc += __shfl_xor_sync(0xffffffffu, acc, o);

        if (lane == 0) {
            const float y = acc + Dd * xsc;
            const float sg = zc / (1.f + __expf(-zc));
            const float yv = y * sg;
            const __half hy = __float2half_rn(yv);
            const __half ly = __float2half_rn(yv - __half2float(hy));
            g_yh[(size_t)m * DINNER + d] = hy;
            g_yl[(size_t)m * DINNER + d] = ly;
        }
        m++;
    }
    ((float2*)state_out)[(size_t)(b * DINNER + d) * 32 + lane] = make_float2(s0, s1);
}

// ---------------- launch ----------------
extern "C" void kernel_launch(void* const* d_in, const int* in_sizes, int n_in,
                              void* d_out, int out_size)
{
    const float* x          = (const float*)d_in[0];
    const float* in_proj_w  = (const float*)d_in[1];
    const float* conv_w     = (const float*)d_in[2];
    const float* conv_b     = (const float*)d_in[3];
    const float* x_proj_w   = (const float*)d_in[4];
    const float* dt_w       = (const float*)d_in[5];
    const float* dt_b       = (const float*)d_in[6];
    const float* A_log      = (const float*)d_in[7];
    const float* Dp         = (const float*)d_in[8];
    const float* out_proj_w = (const float*)d_in[9];
    float* out = (float*)d_out;

    void* p;
    cudaGetSymbolAddress(&p, g_xz);  float*  p_xz  = (float*)p;
    cudaGetSymbolAddress(&p, g_xh);  __half* p_xh  = (__half*)p;
    cudaGetSymbolAddress(&p, g_xl);  __half* p_xl  = (__half*)p;
    cudaGetSymbolAddress(&p, g_w1h); __half* p_w1h = (__half*)p;
    cudaGetSymbolAddress(&p, g_w1l); __half* p_w1l = (__half*)p;
    cudaGetSymbolAddress(&p, g_w3h); __half* p_w3h = (__half*)p;
    cudaGetSymbolAddress(&p, g_w3l); __half* p_w3l = (__half*)p;
    cudaGetSymbolAddress(&p, g_yh);  __half* p_yh  = (__half*)p;
    cudaGetSymbolAddress(&p, g_yl);  __half* p_yl  = (__half*)p;

    cudaFuncSetAttribute(gemm_hl, cudaFuncAttributeMaxDynamicSharedMemorySize, GSMEM);

    // zero C for split-K GEMM3
    cudaMemsetAsync(out, 0, (size_t)OUT_ELEMS * sizeof(float));

    // 0) pre-passes
    cvt_x_kernel<<<(MROWS * DMODEL) / 1024, 256>>>(x);
    tconv_kernel<<<dim3(2 * DINNER / 32, DMODEL / 32), dim3(32, 8)>>>(
        in_proj_w, p_w1h, p_w1l, DMODEL, 2 * DINNER);
    tconv_kernel<<<dim3(DMODEL / 32, DINNER / 32), dim3(32, 8)>>>(
        out_proj_w, p_w3h, p_w3l, DINNER, DMODEL);

    // 1) xz = x @ in_proj_w  (M=1024, N=4096, K=1024)
    gemm_hl<<<dim3(2 * DINNER / BN, MROWS / BM, 1), 256, GSMEM>>>(
        p_xh, p_xl, p_w1h, p_w1l, p_xz, MROWS, 2 * DINNER, DMODEL, 1);

    // 2) depthwise causal conv + SiLU
    conv_silu_kernel<<<MROWS, 256>>>(conv_w, conv_b);

    // 3) xp = xs @ x_proj_w (split-K fp32) -> Bm, Cm, dt_raw
    xp_partial_kernel<<<dim3(MROWS / 16, KCH), 160>>>(x_proj_w);
    xp_reduce_kernel<<<MROWS, 160>>>();

    // 4) selective scan (barrier-free) -> yh/yl, final state -> d_out tail
    scan_kernel<<<512, 256>>>(A_log, Dp, dt_w, dt_b, out + OUT_ELEMS);

    // 5) out = y @ out_proj_w (M=1024, N=1024, K=2048), split-K=4
    gemm_hl<<<dim3(DMODEL / BN, MROWS / BM, 4), 256, GSMEM>>>(
        p_yh, p_yl, p_w3h, p_w3l, out, MROWS, DMODEL, DINNER, 4);
}

// round 7
// speedup vs baseline: 1.3924x; 1.0144x over previous
#include <cuda_runtime.h>
#include <cuda_fp16.h>
#include <math.h>
#include <stdint.h>

// ---------------- problem constants ----------------
#define BSZ   2
#define LSEQ  512
#define DMODEL 1024
#define DINNER 2048
#define DSTATE 64
#define KCONV 4
#define MROWS (BSZ*LSEQ)     // 1024
#define NXP   129
#define KCH   8
#define KSZ   (DINNER/KCH)
#define OUT_ELEMS (MROWS*DMODEL)

// ---------------- device scratch ----------------
__device__ __align__(16) float g_xz  [MROWS * 2 * DINNER];
__device__ __align__(16) float g_xs  [MROWS * DINNER];
__device__ __align__(16) float g_xpp [KCH * MROWS * NXP];
__device__ __align__(16) float g_Bm  [MROWS * DSTATE];
__device__ __align__(16) float g_Cm  [MROWS * DSTATE];
__device__ __align__(16) float g_dtr [MROWS];
__device__ __align__(16) __half g_xh [MROWS * DMODEL];
__device__ __align__(16) __half g_xl [MROWS * DMODEL];
__device__ __align__(16) __half g_w1h[2 * DINNER * DMODEL];
__device__ __align__(16) __half g_w1l[2 * DINNER * DMODEL];
__device__ __align__(16) __half g_w3h[DMODEL * DINNER];
__device__ __align__(16) __half g_w3l[DMODEL * DINNER];
__device__ __align__(16) __half g_yh [MROWS * DINNER];
__device__ __align__(16) __half g_yl [MROWS * DINNER];

// ================= helpers =================
__device__ __forceinline__ uint32_t smem_u32(const void* p) {
    uint32_t a;
    asm("{ .reg .u64 t; cvta.to.shared.u64 t, %1; cvt.u32.u64 %0, t; }" : "=r"(a) : "l"(p));
    return a;
}
__device__ __forceinline__ void cp16(uint32_t d, const void* s) {
    asm volatile("cp.async.cg.shared.global [%0], [%1], 16;" :: "r"(d), "l"(s));
}
#define CP_COMMIT() asm volatile("cp.async.commit_group;" ::: "memory")
#define CP_WAIT1()  asm volatile("cp.async.wait_group 1;" ::: "memory")

__device__ __forceinline__ void ldsm4(uint32_t& r0, uint32_t& r1, uint32_t& r2, uint32_t& r3, uint32_t a) {
    asm volatile("ldmatrix.sync.aligned.m8n8.x4.shared.b16 {%0,%1,%2,%3}, [%4];"
        : "=r"(r0), "=r"(r1), "=r"(r2), "=r"(r3) : "r"(a));
}

__device__ __forceinline__ void mma16816(float4& d,
    uint32_t a0, uint32_t a1, uint32_t a2, uint32_t a3,
    uint32_t b0, uint32_t b1)
{
    asm("mma.sync.aligned.m16n8k16.row.col.f32.f16.f16.f32 "
        "{%0,%1,%2,%3}, {%4,%5,%6,%7}, {%8,%9}, {%0,%1,%2,%3};"
        : "+f"(d.x), "+f"(d.y), "+f"(d.z), "+f"(d.w)
        : "r"(a0), "r"(a1), "r"(a2), "r"(a3), "r"(b0), "r"(b1));
}

// ================= fp16 hi/lo GEMM =================
// C[M,N] = A[M,K] @ B^T with A as (Ah,Al)[M][K], B^T as (Bh,Bl)[N][K].
// D = Ah*Bh + Ah*Bl + Al*Bh, fp32 accum. ksplit>1 -> atomicAdd into zeroed C.
#define BM 128
#define BN 128
#define BK 32
#define PITCH 40               // halfs per smem row (32 + 8 pad) = 80B
#define TSTG (128*PITCH)
#define STG  (4*TSTG)
#define GSMEM (2*STG*2)        // 81920 bytes

__global__ __launch_bounds__(256, 2) void gemm_hl(
    const __half* __restrict__ Ah, const __half* __restrict__ Al,
    const __half* __restrict__ Bh, const __half* __restrict__ Bl,
    float* __restrict__ C, int M, int N, int K, int ksplit)
{
    extern __shared__ __half sm[];
    const uint32_t sbase = smem_u32(sm);
    const int tid  = threadIdx.x;
    const int lane = tid & 31, warp = tid >> 5;
    const int gid  = lane >> 2, tig = lane & 3;
    const int wm   = warp >> 2, wn = warp & 3;
    const int m0 = blockIdx.y * BM, n0 = blockIdx.x * BN;
    const int kchunk = K / ksplit;
    const int kbeg   = blockIdx.z * kchunk;
    const int NCH    = kchunk / BK;

    // staging: 4 tiles (Ah,Al,Bh,Bl), 64 threads/tile, 8 x 16B each
    const int tile = tid >> 6;
    const int lt   = tid & 63;
    const __half* srcb = (tile == 0) ? Ah : (tile == 1) ? Al : (tile == 2) ? Bh : Bl;
    const int rowoff   = (tile < 2) ? m0 : n0;

    auto issue = [&](int c) {
        const int k0 = kbeg + c * BK;
        const uint32_t sb = sbase + ((c & 1) * STG + tile * TSTG) * 2;
#pragma unroll
        for (int j = 0; j < 8; ++j) {
            int idx = lt * 8 + j;
            int row = idx >> 2, ch = idx & 3;
            cp16(sb + (uint32_t)(row * PITCH + ch * 8) * 2,
                 srcb + (size_t)(rowoff + row) * K + k0 + ch * 8);
        }
    };

    // ldmatrix lane address offsets (bytes within a tile buffer)
    const int matid = lane >> 3, mrow = lane & 7;
    const uint32_t aOff = (uint32_t)((wm * 64 + (matid & 1) * 8 + mrow) * PITCH
                                     + (matid >> 1) * 8) * 2;
    const uint32_t bOff = (uint32_t)((wn * 32 + (matid >> 1) * 8 + mrow) * PITCH
                                     + (matid & 1) * 8) * 2;

    float4 acc[4][4];
#pragma unroll
    for (int i = 0; i < 4; i++)
#pragma unroll
        for (int j = 0; j < 4; j++) acc[i][j] = make_float4(0.f, 0.f, 0.f, 0.f);

    issue(0); CP_COMMIT();
    issue(1); CP_COMMIT();

    for (int c = 0; c < NCH; ++c) {
        CP_WAIT1();
        __syncthreads();

        const uint32_t buf = sbase + (uint32_t)(c & 1) * STG * 2;
        const uint32_t tAh = buf;
        const uint32_t tAl = buf + TSTG * 2;
        const uint32_t tBh = buf + 2 * TSTG * 2;
        const uint32_t tBl = buf + 3 * TSTG * 2;

#pragma unroll
        for (int ks = 0; ks < 2; ++ks) {
            const uint32_t ko = ks * 32;   // 16 halfs
            uint32_t bh[4][2], bl[4][2];
            ldsm4(bh[0][0], bh[0][1], bh[1][0], bh[1][1], tBh + bOff + ko);
            ldsm4(bh[2][0], bh[2][1], bh[3][0], bh[3][1], tBh + bOff + 16 * PITCH * 2 + ko);
            ldsm4(bl[0][0], bl[0][1], bl[1][0], bl[1][1], tBl + bOff + ko);
            ldsm4(bl[2][0], bl[2][1], bl[3][0], bl[3][1], tBl + bOff + 16 * PITCH * 2 + ko);
            // process mf tiles in pairs: 3 passes of 8 independent MMAs each
#pragma unroll
            for (int mp = 0; mp < 2; ++mp) {
                uint32_t ah[2][4], al[2][4];
#pragma unroll
                for (int i = 0; i < 2; ++i) {
                    const uint32_t amo = (uint32_t)((mp * 2 + i) * 16 * PITCH) * 2 + ko;
                    ldsm4(ah[i][0], ah[i][1], ah[i][2], ah[i][3], tAh + aOff + amo);
                    ldsm4(al[i][0], al[i][1], al[i][2], al[i][3], tAl + aOff + amo);
                }
                // pass 1: Ah * Bh
#pragma unroll
                for (int i = 0; i < 2; ++i)
#pragma unroll
                    for (int nf = 0; nf < 4; ++nf)
                        mma16816(acc[mp * 2 + i][nf], ah[i][0], ah[i][1], ah[i][2], ah[i][3],
                                 bh[nf][0], bh[nf][1]);
                // pass 2: Ah * Bl
#pragma unroll
                for (int i = 0; i < 2; ++i)
#pragma unroll
                    for (int nf = 0; nf < 4; ++nf)
                        mma16816(acc[mp * 2 + i][nf], ah[i][0], ah[i][1], ah[i][2], ah[i][3],
                                 bl[nf][0], bl[nf][1]);
                // pass 3: Al * Bh
#pragma unroll
                for (int i = 0; i < 2; ++i)
#pragma unroll
                    for (int nf = 0; nf < 4; ++nf)
                        mma16816(acc[mp * 2 + i][nf], al[i][0], al[i][1], al[i][2], al[i][3],
                                 bh[nf][0], bh[nf][1]);
            }
        }
        __syncthreads();
        if (c + 2 < NCH) issue(c + 2);
        CP_COMMIT();
    }

#pragma unroll
    for (int mf = 0; mf < 4; ++mf)
#pragma unroll
        for (int nf = 0; nf < 4; ++nf) {
            int r  = m0 + wm * 64 + mf * 16 + gid;
            int cc = n0 + wn * 32 + nf * 8 + tig * 2;
            float4 v = acc[mf][nf];
            if (ksplit == 1) {
                *(float2*)(C + (size_t)r * N + cc)       = make_float2(v.x, v.y);
                *(float2*)(C + (size_t)(r + 8) * N + cc) = make_float2(v.z, v.w);
            } else {
                atomicAdd(C + (size_t)r * N + cc,           v.x);
                atomicAdd(C + (size_t)r * N + cc + 1,       v.y);
                atomicAdd(C + (size_t)(r + 8) * N + cc,     v.z);
                atomicAdd(C + (size_t)(r + 8) * N + cc + 1, v.w);
            }
        }
}

// ---------------- pre-pass: x -> fp16 hi/lo ----------------
__global__ void cvt_x_kernel(const float* __restrict__ x)
{
    int i = (blockIdx.x * 256 + threadIdx.x) * 4;
    float4 v = *(const float4*)(x + i);
    __half h0 = __float2half_rn(v.x), h1 = __float2half_rn(v.y);
    __half h2 = __float2half_rn(v.z), h3 = __float2half_rn(v.w);
    __half l0 = __float2half_rn(v.x - __half2float(h0));
    __half l1 = __float2half_rn(v.y - __half2float(h1));
    __half l2 = __float2half_rn(v.z - __half2float(h2));
    __half l3 = __float2half_rn(v.w - __half2float(h3));
    __half hh[4] = {h0, h1, h2, h3};
    __half ll[4] = {l0, l1, l2, l3};
    *(uint2*)(g_xh + i) = *(uint2*)hh;
    *(uint2*)(g_xl + i) = *(uint2*)ll;
}

// ---------------- pre-pass: W [K][N] -> W^T hi/lo [N][K] fp16 ----------------
__global__ void tconv_kernel(const float* __restrict__ W,
                             __half* __restrict__ Th, __half* __restrict__ Tl,
                             int K, int N)
{
    __shared__ float t[32][33];
    const int n0 = blockIdx.x * 32, k0 = blockIdx.y * 32;
    const int tx = threadIdx.x, ty = threadIdx.y;
#pragma unroll
    for (int i = 0; i < 4; ++i)
        t[ty + i * 8][tx] = W[(size_t)(k0 + ty + i * 8) * N + n0 + tx];
    __syncthreads();
#pragma unroll
    for (int i = 0; i < 4; ++i) {
        int r = ty + i * 8;
        float v = t[tx][r];
        __half h = __float2half_rn(v);
        __half l = __float2half_rn(v - __half2float(h));
        Th[(size_t)(n0 + r) * K + k0 + tx] = h;
        Tl[(size_t)(n0 + r) * K + k0 + tx] = l;
    }
}

// ---------------- depthwise causal conv (K=4) + bias + SiLU ----------------
__global__ void conv_silu_kernel(const float* __restrict__ conv_w,
                                 const float* __restrict__ conv_b)
{
    const int m = blockIdx.x;
    const int b = m / LSEQ;
    const int l = m % LSEQ;
    for (int c = threadIdx.x; c < DINNER; c += blockDim.x) {
        float s = conv_b[c];
#pragma unroll
        for (int k = 0; k < KCONV; k++) {
            int ls = l - (KCONV - 1) + k;
            if (ls >= 0)
                s += g_xz[(size_t)(b * LSEQ + ls) * (2 * DINNER) + c] * conv_w[c * KCONV + k];
        }
        float sil = s / (1.f + __expf(-s));
        g_xs[(size_t)m * DINNER + c] = sil;
    }
}

// ---------------- x-proj split-K partials ----------------
__global__ __launch_bounds__(160) void xp_partial_kernel(const float* __restrict__ W)
{
    __shared__ float s[16][KSZ];
    const int m0 = blockIdx.x * 16;
    const int k0 = blockIdx.y * KSZ;
    const int tid = threadIdx.x;

    for (int idx = tid; idx < 16 * KSZ; idx += blockDim.x) {
        int r = idx / KSZ, k = idx % KSZ;
        s[r][k] = g_xs[(size_t)(m0 + r) * DINNER + k0 + k];
    }
    __syncthreads();

    if (tid < NXP) {
        float acc[16];
#pragma unroll
        for (int r = 0; r < 16; r++) acc[r] = 0.f;
        for (int k = 0; k < KSZ; k++) {
            float w = W[(size_t)(k0 + k) * NXP + tid];
#pragma unroll
            for (int r = 0; r < 16; r++) acc[r] += s[r][k] * w;
        }
#pragma unroll
        for (int r = 0; r < 16; r++)
            g_xpp[(size_t)(blockIdx.y * MROWS + m0 + r) * NXP + tid] = acc[r];
    }
}

__global__ __launch_bounds__(160) void xp_reduce_kernel()
{
    const int m = blockIdx.x;
    const int n = threadIdx.x;
    if (n >= NXP) return;
    float sum = 0.f;
#pragma unroll
    for (int kc = 0; kc < KCH; kc++)
        sum += g_xpp[(size_t)(kc * MROWS + m) * NXP + n];
    if (n < DSTATE)            g_Bm[m * DSTATE + n] = sum;
    else if (n < 2 * DSTATE)   g_Cm[m * DSTATE + (n - DSTATE)] = sum;
    else                       g_dtr[m] = sum;
}

// ---------------- selective scan: warp-autonomous, barrier-free -------------
__global__ __launch_bounds__(256) void scan_kernel(
    const float* __restrict__ A_log, const float* __restrict__ Dp,
    const float* __restrict__ dt_w, const float* __restrict__ dt_b,
    float* __restrict__ state_out)
{
    const int warp = threadIdx.x >> 5;
    const int lane = threadIdx.x & 31;
    const int wg = blockIdx.x * 8 + warp;
    const int b = wg >> 11;
    const int d = wg & (DINNER - 1);

    const float a0 = -__expf(A_log[d * DSTATE + 2 * lane]);
    const float a1 = -__expf(A_log[d * DSTATE + 2 * lane + 1]);
    const float Dd = Dp[d];
    const float dw = dt_w[d], db = dt_b[d];

    const float2* B2 = (const float2*)g_Bm;
    const float2* C2 = (const float2*)g_Cm;
    const int mbase = b * LSEQ;
    const int mlast = mbase + LSEQ - 1;

    int m = mbase;
    float2 Bn = B2[(size_t)m * 32 + lane];
    float2 Cn = C2[(size_t)m * 32 + lane];
    float dtrn = g_dtr[m];
    float xsn  = g_xs[(size_t)m * DINNER + d];
    float zn   = g_xz[(size_t)m * (2 * DINNER) + DINNER + d];

    float s0 = 0.f, s1 = 0.f;
    for (int t = 0; t < LSEQ; ++t) {
        const float2 Bc = Bn, Cc = Cn;
        const float dtrc = dtrn, xsc = xsn, zc = zn;

        const int mn = (m < mlast) ? m + 1 : mlast;
        Bn   = B2[(size_t)mn * 32 + lane];
        Cn   = C2[(size_t)mn * 32 + lane];
        dtrn = g_dtr[mn];
        xsn  = g_xs[(size_t)mn * DINNER + d];
        zn   = g_xz[(size_t)mn * (2 * DINNER) + DINNER + d];

        const float v = dtrc * dw + db;
        const float dtv = __logf(1.f + __expf(v));
        const float dx = dtv * xsc;
        s0 = __expf(dtv * a0) * s0 + dx * Bc.x;
        s1 = __expf(dtv * a1) * s1 + dx * Bc.y;

        float acc = s0 * Cc.x + s1 * Cc.y;
#pragma unroll
        for (int o = 16; o; o >>= 1) acc += __shfl_xor_sync(0xffffffffu, acc, o);

        if (lane == 0) {
            const float y = acc + Dd * xsc;
            const float sg = zc / (1.f + __expf(-zc));
            const float yv = y * sg;
            const __half hy = __float2half_rn(yv);
            const __half ly = __float2half_rn(yv - __half2float(hy));
            g_yh[(size_t)m * DINNER + d] = hy;
            g_yl[(size_t)m * DINNER + d] = ly;
        }
        m++;
    }
    ((float2*)state_out)[(size_t)(b * DINNER + d) * 32 + lane] = make_float2(s0, s1);
}

// ---------------- launch ----------------
extern "C" void kernel_launch(void* const* d_in, const int* in_sizes, int n_in,
                              void* d_out, int out_size)
{
    const float* x          = (const float*)d_in[0];
    const float* in_proj_w  = (const float*)d_in[1];
    const float* conv_w     = (const float*)d_in[2];
    const float* conv_b     = (const float*)d_in[3];
    const float* x_proj_w   = (const float*)d_in[4];
    const float* dt_w       = (const float*)d_in[5];
    const float* dt_b       = (const float*)d_in[6];
    const float* A_log      = (const float*)d_in[7];
    const float* Dp         = (const float*)d_in[8];
    const float* out_proj_w = (const float*)d_in[9];
    float* out = (float*)d_out;

    void* p;
    cudaGetSymbolAddress(&p, g_xz);  float*  p_xz  = (float*)p;
    cudaGetSymbolAddress(&p, g_xh);  __half* p_xh  = (__half*)p;
    cudaGetSymbolAddress(&p, g_xl);  __half* p_xl  = (__half*)p;
    cudaGetSymbolAddress(&p, g_w1h); __half* p_w1h = (__half*)p;
    cudaGetSymbolAddress(&p, g_w1l); __half* p_w1l = (__half*)p;
    cudaGetSymbolAddress(&p, g_w3h); __half* p_w3h = (__half*)p;
    cudaGetSymbolAddress(&p, g_w3l); __half* p_w3l = (__half*)p;
    cudaGetSymbolAddress(&p, g_yh);  __half* p_yh  = (__half*)p;
    cudaGetSymbolAddress(&p, g_yl);  __half* p_yl  = (__half*)p;

    cudaFuncSetAttribute(gemm_hl, cudaFuncAttributeMaxDynamicSharedMemorySize, GSMEM);

    cudaMemsetAsync(out, 0, (size_t)OUT_ELEMS * sizeof(float));

    // 0) pre-passes
    cvt_x_kernel<<<(MROWS * DMODEL) / 1024, 256>>>(x);
    tconv_kernel<<<dim3(2 * DINNER / 32, DMODEL / 32), dim3(32, 8)>>>(
        in_proj_w, p_w1h, p_w1l, DMODEL, 2 * DINNER);
    tconv_kernel<<<dim3(DMODEL / 32, DINNER / 32), dim3(32, 8)>>>(
        out_proj_w, p_w3h, p_w3l, DINNER, DMODEL);

    // 1) xz = x @ in_proj_w
    gemm_hl<<<dim3(2 * DINNER / BN, MROWS / BM, 1), 256, GSMEM>>>(
        p_xh, p_xl, p_w1h, p_w1l, p_xz, MROWS, 2 * DINNER, DMODEL, 1);

    // 2) conv + SiLU
    conv_silu_kernel<<<MROWS, 256>>>(conv_w, conv_b);

    // 3) x-proj
    xp_partial_kernel<<<dim3(MROWS / 16, KCH), 160>>>(x_proj_w);
    xp_reduce_kernel<<<MROWS, 160>>>();

    // 4) selective scan
    scan_kernel<<<512, 256>>>(A_log, Dp, dt_w, dt_b, out + OUT_ELEMS);

    // 5) out = y @ out_proj_w, split-K=4
    gemm_hl<<<dim3(DMODEL / BN, MROWS / BM, 4), 256, GSMEM>>>(
        p_yh, p_yl, p_w3h, p_w3l, out, MROWS, DMODEL, DINNER, 4);
}

// round 8
// speedup vs baseline: 1.8112x; 1.3008x over previous
#include <cuda_runtime.h>
#include <cuda_fp16.h>
#include <math.h>
#include <stdint.h>

// ---------------- problem constants ----------------
#define BSZ   2
#define LSEQ  512
#define DMODEL 1024
#define DINNER 2048
#define DSTATE 64
#define KCONV 4
#define MROWS (BSZ*LSEQ)     // 1024
#define NXP   129
#define KCH   8
#define KSZ   (DINNER/KCH)
#define OUT_ELEMS (MROWS*DMODEL)

// ---------------- device scratch ----------------
__device__ __align__(16) float g_xz  [MROWS * 2 * DINNER];
__device__ __align__(16) float g_xs  [MROWS * DINNER];
__device__ __align__(16) float g_sg  [MROWS * DINNER];   // silu(z)
__device__ __align__(16) float g_dtf [MROWS * DINNER];   // softplus dt
__device__ __align__(16) float g_xpp [KCH * MROWS * NXP];
__device__ __align__(16) float g_Bm  [MROWS * DSTATE];
__device__ __align__(16) float g_Cm  [MROWS * DSTATE];
__device__ __align__(16) float g_dtr [MROWS];
__device__ __align__(16) __half g_xh [MROWS * DMODEL];
__device__ __align__(16) __half g_w1h[2 * DINNER * DMODEL];
__device__ __align__(16) __half g_w1l[2 * DINNER * DMODEL];
__device__ __align__(16) __half g_w3h[DMODEL * DINNER];
__device__ __align__(16) __half g_w3l[DMODEL * DINNER];
__device__ __align__(16) __half g_yh [MROWS * DINNER];

// ================= helpers =================
__device__ __forceinline__ uint32_t smem_u32(const void* p) {
    uint32_t a;
    asm("{ .reg .u64 t; cvta.to.shared.u64 t, %1; cvt.u32.u64 %0, t; }" : "=r"(a) : "l"(p));
    return a;
}
__device__ __forceinline__ void cp16(uint32_t d, const void* s) {
    asm volatile("cp.async.cg.shared.global [%0], [%1], 16;" :: "r"(d), "l"(s));
}
#define CP_COMMIT() asm volatile("cp.async.commit_group;" ::: "memory")
#define CP_WAIT1()  asm volatile("cp.async.wait_group 1;" ::: "memory")

__device__ __forceinline__ void ldsm4(uint32_t& r0, uint32_t& r1, uint32_t& r2, uint32_t& r3, uint32_t a) {
    asm volatile("ldmatrix.sync.aligned.m8n8.x4.shared.b16 {%0,%1,%2,%3}, [%4];"
        : "=r"(r0), "=r"(r1), "=r"(r2), "=r"(r3) : "r"(a));
}

__device__ __forceinline__ void mma16816(float4& d,
    uint32_t a0, uint32_t a1, uint32_t a2, uint32_t a3,
    uint32_t b0, uint32_t b1)
{
    asm("mma.sync.aligned.m16n8k16.row.col.f32.f16.f16.f32 "
        "{%0,%1,%2,%3}, {%4,%5,%6,%7}, {%8,%9}, {%0,%1,%2,%3};"
        : "+f"(d.x), "+f"(d.y), "+f"(d.z), "+f"(d.w)
        : "r"(a0), "r"(a1), "r"(a2), "r"(a3), "r"(b0), "r"(b1));
}

// ================= fp16 x2 GEMM =================
// C[M,N] = A[M,K] @ B^T, A fp16 [M][K], B^T as (Bh,Bl) [N][K] hi/lo fp16.
// D = A*Bh + A*Bl, fp32 accum. ksplit>1 -> atomicAdd into zeroed C.
#define BM 128
#define BN 128
#define BK 32
#define PITCH 40               // halfs per smem row (32 + 8 pad) = 80B
#define TSTG (128*PITCH)
#define STG3 (3*TSTG)
#define GSMEM (2*STG3*2)       // 61440 bytes

__global__ __launch_bounds__(256, 2) void gemm_a16(
    const __half* __restrict__ A,
    const __half* __restrict__ Bh, const __half* __restrict__ Bl,
    float* __restrict__ C, int M, int N, int K, int ksplit)
{
    extern __shared__ __half sm[];
    const uint32_t sbase = smem_u32(sm);
    const int tid  = threadIdx.x;
    const int lane = tid & 31, warp = tid >> 5;
    const int gid  = lane >> 2, tig = lane & 3;
    const int wm   = warp >> 2, wn = warp & 3;
    const int m0 = blockIdx.y * BM, n0 = blockIdx.x * BN;
    const int kchunk = K / ksplit;
    const int kbeg   = blockIdx.z * kchunk;
    const int NCH    = kchunk / BK;

    // staging: tids 0-127 -> A (1 row x 4 chunks), 128-191 -> Bh (2 rows),
    //          192-255 -> Bl (2 rows)
    auto issue = [&](int c) {
        const int k0 = kbeg + c * BK;
        const uint32_t stg = sbase + (uint32_t)(c & 1) * STG3 * 2;
        if (tid < 128) {
            const uint32_t sb = stg + (uint32_t)(tid * PITCH) * 2;
            const __half* src = A + (size_t)(m0 + tid) * K + k0;
#pragma unroll
            for (int j = 0; j < 4; ++j)
                cp16(sb + j * 16, src + j * 8);
        } else {
            const __half* wsrc = (tid < 192) ? Bh : Bl;
            const uint32_t tb = stg + (uint32_t)((tid < 192) ? 1 : 2) * TSTG * 2;
            const int r0 = (tid & 63) * 2;
#pragma unroll
            for (int rr = 0; rr < 2; ++rr) {
                const uint32_t sb = tb + (uint32_t)((r0 + rr) * PITCH) * 2;
                const __half* src = wsrc + (size_t)(n0 + r0 + rr) * K + k0;
#pragma unroll
                for (int j = 0; j < 4; ++j)
                    cp16(sb + j * 16, src + j * 8);
            }
        }
    };

    // ldmatrix lane address offsets (bytes within a tile buffer)
    const int matid = lane >> 3, mrow = lane & 7;
    const uint32_t aOff = (uint32_t)((wm * 64 + (matid & 1) * 8 + mrow) * PITCH
                                     + (matid >> 1) * 8) * 2;
    const uint32_t bOff = (uint32_t)((wn * 32 + (matid >> 1) * 8 + mrow) * PITCH
                                     + (matid & 1) * 8) * 2;

    float4 acc[4][4];
#pragma unroll
    for (int i = 0; i < 4; i++)
#pragma unroll
        for (int j = 0; j < 4; j++) acc[i][j] = make_float4(0.f, 0.f, 0.f, 0.f);

    issue(0); CP_COMMIT();
    issue(1); CP_COMMIT();

    for (int c = 0; c < NCH; ++c) {
        CP_WAIT1();
        __syncthreads();

        const uint32_t buf = sbase + (uint32_t)(c & 1) * STG3 * 2;
        const uint32_t tA  = buf;
        const uint32_t tBh = buf + TSTG * 2;
        const uint32_t tBl = buf + 2 * TSTG * 2;

#pragma unroll
        for (int ks = 0; ks < 2; ++ks) {
            const uint32_t ko = ks * 32;   // 16 halfs
            uint32_t av[4][4];
#pragma unroll
            for (int mf = 0; mf < 4; ++mf)
                ldsm4(av[mf][0], av[mf][1], av[mf][2], av[mf][3],
                      tA + aOff + (uint32_t)(mf * 16 * PITCH) * 2 + ko);
            uint32_t bh[4][2], bl[4][2];
            ldsm4(bh[0][0], bh[0][1], bh[1][0], bh[1][1], tBh + bOff + ko);
            ldsm4(bh[2][0], bh[2][1], bh[3][0], bh[3][1], tBh + bOff + 16 * PITCH * 2 + ko);
            ldsm4(bl[0][0], bl[0][1], bl[1][0], bl[1][1], tBl + bOff + ko);
            ldsm4(bl[2][0], bl[2][1], bl[3][0], bl[3][1], tBl + bOff + 16 * PITCH * 2 + ko);
            // pass 1: A * Bh  (16 independent)
#pragma unroll
            for (int mf = 0; mf < 4; ++mf)
#pragma unroll
                for (int nf = 0; nf < 4; ++nf)
                    mma16816(acc[mf][nf], av[mf][0], av[mf][1], av[mf][2], av[mf][3],
                             bh[nf][0], bh[nf][1]);
            // pass 2: A * Bl  (16 independent)
#pragma unroll
            for (int mf = 0; mf < 4; ++mf)
#pragma unroll
                for (int nf = 0; nf < 4; ++nf)
                    mma16816(acc[mf][nf], av[mf][0], av[mf][1], av[mf][2], av[mf][3],
                             bl[nf][0], bl[nf][1]);
        }
        __syncthreads();
        if (c + 2 < NCH) issue(c + 2);
        CP_COMMIT();
    }

#pragma unroll
    for (int mf = 0; mf < 4; ++mf)
#pragma unroll
        for (int nf = 0; nf < 4; ++nf) {
            int r  = m0 + wm * 64 + mf * 16 + gid;
            int cc = n0 + wn * 32 + nf * 8 + tig * 2;
            float4 v = acc[mf][nf];
            if (ksplit == 1) {
                *(float2*)(C + (size_t)r * N + cc)       = make_float2(v.x, v.y);
                *(float2*)(C + (size_t)(r + 8) * N + cc) = make_float2(v.z, v.w);
            } else {
                atomicAdd(C + (size_t)r * N + cc,           v.x);
                atomicAdd(C + (size_t)r * N + cc + 1,       v.y);
                atomicAdd(C + (size_t)(r + 8) * N + cc,     v.z);
                atomicAdd(C + (size_t)(r + 8) * N + cc + 1, v.w);
            }
        }
}

// ---------------- pre-pass: x -> fp16 ----------------
__global__ void cvt_x_kernel(const float* __restrict__ x)
{
    int i = (blockIdx.x * 256 + threadIdx.x) * 4;
    float4 v = *(const float4*)(x + i);
    __half hh[4] = {__float2half_rn(v.x), __float2half_rn(v.y),
                    __float2half_rn(v.z), __float2half_rn(v.w)};
    *(uint2*)(g_xh + i) = *(uint2*)hh;
}

// ---------------- pre-pass: W [K][N] -> W^T hi/lo [N][K] fp16 ----------------
__global__ void tconv_kernel(const float* __restrict__ W,
                             __half* __restrict__ Th, __half* __restrict__ Tl,
                             int K, int N)
{
    __shared__ float t[32][33];
    const int n0 = blockIdx.x * 32, k0 = blockIdx.y * 32;
    const int tx = threadIdx.x, ty = threadIdx.y;
#pragma unroll
    for (int i = 0; i < 4; ++i)
        t[ty + i * 8][tx] = W[(size_t)(k0 + ty + i * 8) * N + n0 + tx];
    __syncthreads();
#pragma unroll
    for (int i = 0; i < 4; ++i) {
        int r = ty + i * 8;
        float v = t[tx][r];
        __half h = __float2half_rn(v);
        __half l = __float2half_rn(v - __half2float(h));
        Th[(size_t)(n0 + r) * K + k0 + tx] = h;
        Tl[(size_t)(n0 + r) * K + k0 + tx] = l;
    }
}

// -------- depthwise causal conv (K=4) + bias + SiLU; also silu(z) --------
__global__ void conv_silu_kernel(const float* __restrict__ conv_w,
                                 const float* __restrict__ conv_b)
{
    const int m = blockIdx.x;
    const int b = m / LSEQ;
    const int l = m % LSEQ;
    for (int c = threadIdx.x; c < DINNER; c += blockDim.x) {
        float s = conv_b[c];
#pragma unroll
        for (int k = 0; k < KCONV; k++) {
            int ls = l - (KCONV - 1) + k;
            if (ls >= 0)
                s += g_xz[(size_t)(b * LSEQ + ls) * (2 * DINNER) + c] * conv_w[c * KCONV + k];
        }
        g_xs[(size_t)m * DINNER + c] = s / (1.f + __expf(-s));
        float z = g_xz[(size_t)m * (2 * DINNER) + DINNER + c];
        g_sg[(size_t)m * DINNER + c] = z / (1.f + __expf(-z));
    }
}

// ---------------- x-proj split-K partials ----------------
__global__ __launch_bounds__(160) void xp_partial_kernel(const float* __restrict__ W)
{
    __shared__ float s[16][KSZ];
    const int m0 = blockIdx.x * 16;
    const int k0 = blockIdx.y * KSZ;
    const int tid = threadIdx.x;

    for (int idx = tid; idx < 16 * KSZ; idx += blockDim.x) {
        int r = idx / KSZ, k = idx % KSZ;
        s[r][k] = g_xs[(size_t)(m0 + r) * DINNER + k0 + k];
    }
    __syncthreads();

    if (tid < NXP) {
        float acc[16];
#pragma unroll
        for (int r = 0; r < 16; r++) acc[r] = 0.f;
        for (int k = 0; k < KSZ; k++) {
            float w = W[(size_t)(k0 + k) * NXP + tid];
#pragma unroll
            for (int r = 0; r < 16; r++) acc[r] += s[r][k] * w;
        }
#pragma unroll
        for (int r = 0; r < 16; r++)
            g_xpp[(size_t)(blockIdx.y * MROWS + m0 + r) * NXP + tid] = acc[r];
    }
}

__global__ __launch_bounds__(160) void xp_reduce_kernel()
{
    const int m = blockIdx.x;
    const int n = threadIdx.x;
    if (n >= NXP) return;
    float sum = 0.f;
#pragma unroll
    for (int kc = 0; kc < KCH; kc++)
        sum += g_xpp[(size_t)(kc * MROWS + m) * NXP + n];
    if (n < DSTATE)            g_Bm[m * DSTATE + n] = sum;
    else if (n < 2 * DSTATE)   g_Cm[m * DSTATE + (n - DSTATE)] = sum;
    else                       g_dtr[m] = sum;
}

// ---------------- dt = softplus(dt_raw * dt_w + dt_b), elementwise ----------
__global__ void dt_pre_kernel(const float* __restrict__ dt_w,
                              const float* __restrict__ dt_b)
{
    const int m = blockIdx.x;
    const float dr = g_dtr[m];
    for (int c = threadIdx.x; c < DINNER; c += blockDim.x) {
        float v = dr * dt_w[c] + dt_b[c];
        g_dtf[(size_t)m * DINNER + c] = (v > 20.f) ? v : log1pf(__expf(v));
    }
}

// ---------------- selective scan: warp-autonomous, 2 MUFU per t -------------
__global__ __launch_bounds__(256) void scan_kernel(
    const float* __restrict__ A_log, const float* __restrict__ Dp,
    float* __restrict__ state_out)
{
    const int warp = threadIdx.x >> 5;
    const int lane = threadIdx.x & 31;
    const int wg = blockIdx.x * 8 + warp;
    const int b = wg >> 11;
    const int d = wg & (DINNER - 1);

    const float a0 = -__expf(A_log[d * DSTATE + 2 * lane]);
    const float a1 = -__expf(A_log[d * DSTATE + 2 * lane + 1]);
    const float Dd = Dp[d];

    const float2* B2 = (const float2*)g_Bm;
    const float2* C2 = (const float2*)g_Cm;
    const int mbase = b * LSEQ;
    const int mlast = mbase + LSEQ - 1;

    int m = mbase;
    float2 Bn = B2[(size_t)m * 32 + lane];
    float2 Cn = C2[(size_t)m * 32 + lane];
    float dtn = g_dtf[(size_t)m * DINNER + d];
    float xsn = g_xs[(size_t)m * DINNER + d];
    float sgn = g_sg[(size_t)m * DINNER + d];

    float s0 = 0.f, s1 = 0.f;
    for (int t = 0; t < LSEQ; ++t) {
        const float2 Bc = Bn, Cc = Cn;
        const float dtv = dtn, xsc = xsn, sgc = sgn;

        const int mn = (m < mlast) ? m + 1 : mlast;
        Bn  = B2[(size_t)mn * 32 + lane];
        Cn  = C2[(size_t)mn * 32 + lane];
        dtn = g_dtf[(size_t)mn * DINNER + d];
        xsn = g_xs[(size_t)mn * DINNER + d];
        sgn = g_sg[(size_t)mn * DINNER + d];

        const float dx = dtv * xsc;
        s0 = __expf(dtv * a0) * s0 + dx * Bc.x;
        s1 = __expf(dtv * a1) * s1 + dx * Bc.y;

        float acc = s0 * Cc.x + s1 * Cc.y;
#pragma unroll
        for (int o = 16; o; o >>= 1) acc += __shfl_xor_sync(0xffffffffu, acc, o);

        if (lane == 0) {
            const float yv = (acc + Dd * xsc) * sgc;
            g_yh[(size_t)m * DINNER + d] = __float2half_rn(yv);
        }
        m++;
    }
    ((float2*)state_out)[(size_t)(b * DINNER + d) * 32 + lane] = make_float2(s0, s1);
}

// ---------------- launch ----------------
extern "C" void kernel_launch(void* const* d_in, const int* in_sizes, int n_in,
                              void* d_out, int out_size)
{
    const float* x          = (const float*)d_in[0];
    const float* in_proj_w  = (const float*)d_in[1];
    const float* conv_w     = (const float*)d_in[2];
    const float* conv_b     = (const float*)d_in[3];
    const float* x_proj_w   = (const float*)d_in[4];
    const float* dt_w       = (const float*)d_in[5];
    const float* dt_b       = (const float*)d_in[6];
    const float* A_log      = (const float*)d_in[7];
    const float* Dp         = (const float*)d_in[8];
    const float* out_proj_w = (const float*)d_in[9];
    float* out = (float*)d_out;

    void* p;
    cudaGetSymbolAddress(&p, g_xz);  float*  p_xz  = (float*)p;
    cudaGetSymbolAddress(&p, g_xh);  __half* p_xh  = (__half*)p;
    cudaGetSymbolAddress(&p, g_w1h); __half* p_w1h = (__half*)p;
    cudaGetSymbolAddress(&p, g_w1l); __half* p_w1l = (__half*)p;
    cudaGetSymbolAddress(&p, g_w3h); __half* p_w3h = (__half*)p;
    cudaGetSymbolAddress(&p, g_w3l); __half* p_w3l = (__half*)p;
    cudaGetSymbolAddress(&p, g_yh);  __half* p_yh  = (__half*)p;

    cudaFuncSetAttribute(gemm_a16, cudaFuncAttributeMaxDynamicSharedMemorySize, GSMEM);

    cudaMemsetAsync(out, 0, (size_t)OUT_ELEMS * sizeof(float));

    // 0) pre-passes
    cvt_x_kernel<<<(MROWS * DMODEL) / 1024, 256>>>(x);
    tconv_kernel<<<dim3(2 * DINNER / 32, DMODEL / 32), dim3(32, 8)>>>(
        in_proj_w, p_w1h, p_w1l, DMODEL, 2 * DINNER);
    tconv_kernel<<<dim3(DMODEL / 32, DINNER / 32), dim3(32, 8)>>>(
        out_proj_w, p_w3h, p_w3l, DINNER, DMODEL);

    // 1) xz = x @ in_proj_w
    gemm_a16<<<dim3(2 * DINNER / BN, MROWS / BM, 1), 256, GSMEM>>>(
        p_xh, p_w1h, p_w1l, p_xz, MROWS, 2 * DINNER, DMODEL, 1);

    // 2) conv + SiLU (+ silu(z))
    conv_silu_kernel<<<MROWS, 256>>>(conv_w, conv_b);

    // 3) x-proj
    xp_partial_kernel<<<dim3(MROWS / 16, KCH), 160>>>(x_proj_w);
    xp_reduce_kernel<<<MROWS, 160>>>();

    // 3b) dt softplus precompute
    dt_pre_kernel<<<MROWS, 256>>>(dt_w, dt_b);

    // 4) selective scan
    scan_kernel<<<512, 256>>>(A_log, Dp, out + OUT_ELEMS);

    // 5) out = y @ out_proj_w, split-K=4
    gemm_a16<<<dim3(DMODEL / BN, MROWS / BM, 4), 256, GSMEM>>>(
        p_yh, p_w3h, p_w3l, out, MROWS, DMODEL, DINNER, 4);
}

// round 9
// speedup vs baseline: 1.8548x; 1.0241x over previous
#include <cuda_runtime.h>
#include <cuda_fp16.h>
#include <math.h>
#include <stdint.h>

// ---------------- problem constants ----------------
#define BSZ   2
#define LSEQ  512
#define DMODEL 1024
#define DINNER 2048
#define DSTATE 64
#define KCONV 4
#define MROWS (BSZ*LSEQ)     // 1024
#define NXP   129
#define KCH   8
#define KSZ   (DINNER/KCH)
#define OUT_ELEMS (MROWS*DMODEL)

// ---------------- device scratch ----------------
__device__ __align__(16) float g_xz  [MROWS * 2 * DINNER];
__device__ __align__(16) float g_xs  [MROWS * DINNER];
__device__ __align__(16) float g_sg  [MROWS * DINNER];   // silu(z)
__device__ __align__(16) float g_dtf [MROWS * DINNER];   // softplus dt
__device__ __align__(16) float g_xpp [KCH * MROWS * NXP];
__device__ __align__(16) float g_Bm  [MROWS * DSTATE];
__device__ __align__(16) float g_Cm  [MROWS * DSTATE];
__device__ __align__(16) float g_dtr [MROWS];
__device__ __align__(16) __half g_xh [MROWS * DMODEL];
__device__ __align__(16) __half g_w1h[2 * DINNER * DMODEL];
__device__ __align__(16) __half g_w1l[2 * DINNER * DMODEL];
__device__ __align__(16) __half g_w3h[DMODEL * DINNER];
__device__ __align__(16) __half g_w3l[DMODEL * DINNER];
__device__ __align__(16) __half g_yh [MROWS * DINNER];

// ================= helpers =================
__device__ __forceinline__ uint32_t smem_u32(const void* p) {
    uint32_t a;
    asm("{ .reg .u64 t; cvta.to.shared.u64 t, %1; cvt.u32.u64 %0, t; }" : "=r"(a) : "l"(p));
    return a;
}
__device__ __forceinline__ void cp16(uint32_t d, const void* s) {
    asm volatile("cp.async.cg.shared.global [%0], [%1], 16;" :: "r"(d), "l"(s));
}
#define CP_COMMIT() asm volatile("cp.async.commit_group;" ::: "memory")
#define CP_WAIT1()  asm volatile("cp.async.wait_group 1;" ::: "memory")

__device__ __forceinline__ void ldsm4(uint32_t& r0, uint32_t& r1, uint32_t& r2, uint32_t& r3, uint32_t a) {
    asm volatile("ldmatrix.sync.aligned.m8n8.x4.shared.b16 {%0,%1,%2,%3}, [%4];"
        : "=r"(r0), "=r"(r1), "=r"(r2), "=r"(r3) : "r"(a));
}

__device__ __forceinline__ void mma16816(float4& d,
    uint32_t a0, uint32_t a1, uint32_t a2, uint32_t a3,
    uint32_t b0, uint32_t b1)
{
    asm("mma.sync.aligned.m16n8k16.row.col.f32.f16.f16.f32 "
        "{%0,%1,%2,%3}, {%4,%5,%6,%7}, {%8,%9}, {%0,%1,%2,%3};"
        : "+f"(d.x), "+f"(d.y), "+f"(d.z), "+f"(d.w)
        : "r"(a0), "r"(a1), "r"(a2), "r"(a3), "r"(b0), "r"(b1));
}

// ================= fp16 x2 GEMM, 3-stage pipeline, 3 CTAs/SM =================
// C[M,N] = A[M,K] @ B^T, A fp16 [M][K], B^T as (Bh,Bl) [N][K] hi/lo fp16.
// D = A*Bh + A*Bl, fp32 accum. ksplit>1 -> atomicAdd into zeroed C.
// CTA tile 128x64, warp tile 32x32 (8 warps = 4 wm x 2 wn), BK=32.
#define BM 128
#define BN 64
#define BK 32
#define PITCH 40                     // halfs per smem row (32 + 8 pad) = 80B
#define ATSTG (128*PITCH)            // A tile: 5120 halfs
#define BTSTG (64*PITCH)             // B tile: 2560 halfs
#define STG3  (ATSTG + 2*BTSTG)      // 10240 halfs / stage
#define GSMEM (3*STG3*2)             // 61440 bytes (3 stages)

__global__ __launch_bounds__(256, 3) void gemm_a16(
    const __half* __restrict__ A,
    const __half* __restrict__ Bh, const __half* __restrict__ Bl,
    float* __restrict__ C, int M, int N, int K, int ksplit)
{
    extern __shared__ __half sm[];
    const uint32_t sbase = smem_u32(sm);
    const int tid  = threadIdx.x;
    const int lane = tid & 31, warp = tid >> 5;
    const int gid  = lane >> 2, tig = lane & 3;
    const int wm   = warp >> 1, wn = warp & 1;
    const int m0 = blockIdx.y * BM, n0 = blockIdx.x * BN;
    const int kchunk = K / ksplit;
    const int kbeg   = blockIdx.z * kchunk;
    const int NCH    = kchunk / BK;

    // staging: tid<128 -> A row tid (4x16B); 128-191 -> Bh row tid-128; 192-255 -> Bl
    const __half* srow;
    uint32_t soff;
    {
        if (tid < 128) {
            srow = A + (size_t)(m0 + tid) * K + kbeg;
            soff = (uint32_t)(tid * PITCH) * 2;
        } else if (tid < 192) {
            srow = Bh + (size_t)(n0 + tid - 128) * K + kbeg;
            soff = (uint32_t)(ATSTG + (tid - 128) * PITCH) * 2;
        } else {
            srow = Bl + (size_t)(n0 + tid - 192) * K + kbeg;
            soff = (uint32_t)(ATSTG + BTSTG + (tid - 192) * PITCH) * 2;
        }
    }
    auto issue = [&](int c) {
        const uint32_t sb = sbase + (uint32_t)(c % 3) * (STG3 * 2) + soff;
        const __half* src = srow + c * BK;
#pragma unroll
        for (int j = 0; j < 4; ++j)
            cp16(sb + j * 16, src + j * 8);
    };

    // ldmatrix lane address offsets (bytes within a stage)
    const int matid = lane >> 3, mrow = lane & 7;
    const uint32_t aOff = (uint32_t)((wm * 32 + (matid & 1) * 8 + mrow) * PITCH
                                     + (matid >> 1) * 8) * 2;
    const uint32_t bOff = (uint32_t)(ATSTG + (wn * 32 + (matid >> 1) * 8 + mrow) * PITCH
                                     + (matid & 1) * 8) * 2;

    float4 acc[2][4];
#pragma unroll
    for (int i = 0; i < 2; i++)
#pragma unroll
        for (int j = 0; j < 4; j++) acc[i][j] = make_float4(0.f, 0.f, 0.f, 0.f);

    issue(0); CP_COMMIT();
    issue(1); CP_COMMIT();

    for (int c = 0; c < NCH; ++c) {
        CP_WAIT1();            // stage c landed (per-thread)
        __syncthreads();       // visible to all; all warps done with stage (c-1)%3
        if (c + 2 < NCH) issue(c + 2);
        CP_COMMIT();

        const uint32_t buf = sbase + (uint32_t)(c % 3) * (STG3 * 2);

#pragma unroll
        for (int ks = 0; ks < 2; ++ks) {
            const uint32_t ko = ks * 32;   // 16 halfs
            uint32_t av[2][4];
#pragma unroll
            for (int mf = 0; mf < 2; ++mf)
                ldsm4(av[mf][0], av[mf][1], av[mf][2], av[mf][3],
                      buf + aOff + (uint32_t)(mf * 16 * PITCH) * 2 + ko);
            uint32_t bh[4][2], bl[4][2];
            ldsm4(bh[0][0], bh[0][1], bh[1][0], bh[1][1], buf + bOff + ko);
            ldsm4(bh[2][0], bh[2][1], bh[3][0], bh[3][1], buf + bOff + 16 * PITCH * 2 + ko);
            ldsm4(bl[0][0], bl[0][1], bl[1][0], bl[1][1], buf + BTSTG * 2 + bOff + ko);
            ldsm4(bl[2][0], bl[2][1], bl[3][0], bl[3][1], buf + BTSTG * 2 + bOff + 16 * PITCH * 2 + ko);
            // pass 1: A * Bh (8 independent)
#pragma unroll
            for (int mf = 0; mf < 2; ++mf)
#pragma unroll
                for (int nf = 0; nf < 4; ++nf)
                    mma16816(acc[mf][nf], av[mf][0], av[mf][1], av[mf][2], av[mf][3],
                             bh[nf][0], bh[nf][1]);
            // pass 2: A * Bl (8 independent)
#pragma unroll
            for (int mf = 0; mf < 2; ++mf)
#pragma unroll
                for (int nf = 0; nf < 4; ++nf)
                    mma16816(acc[mf][nf], av[mf][0], av[mf][1], av[mf][2], av[mf][3],
                             bl[nf][0], bl[nf][1]);
        }
    }

#pragma unroll
    for (int mf = 0; mf < 2; ++mf)
#pragma unroll
        for (int nf = 0; nf < 4; ++nf) {
            int r  = m0 + wm * 32 + mf * 16 + gid;
            int cc = n0 + wn * 32 + nf * 8 + tig * 2;
            float4 v = acc[mf][nf];
            if (ksplit == 1) {
                *(float2*)(C + (size_t)r * N + cc)       = make_float2(v.x, v.y);
                *(float2*)(C + (size_t)(r + 8) * N + cc) = make_float2(v.z, v.w);
            } else {
                atomicAdd(C + (size_t)r * N + cc,           v.x);
                atomicAdd(C + (size_t)r * N + cc + 1,       v.y);
                atomicAdd(C + (size_t)(r + 8) * N + cc,     v.z);
                atomicAdd(C + (size_t)(r + 8) * N + cc + 1, v.w);
            }
        }
}

// ---------------- pre-pass: x -> fp16 ----------------
__global__ void cvt_x_kernel(const float* __restrict__ x)
{
    int i = (blockIdx.x * 256 + threadIdx.x) * 4;
    float4 v = *(const float4*)(x + i);
    __half hh[4] = {__float2half_rn(v.x), __float2half_rn(v.y),
                    __float2half_rn(v.z), __float2half_rn(v.w)};
    *(uint2*)(g_xh + i) = *(uint2*)hh;
}

// ---------------- pre-pass: W [K][N] -> W^T hi/lo [N][K] fp16 ----------------
__global__ void tconv_kernel(const float* __restrict__ W,
                             __half* __restrict__ Th, __half* __restrict__ Tl,
                             int K, int N)
{
    __shared__ float t[32][33];
    const int n0 = blockIdx.x * 32, k0 = blockIdx.y * 32;
    const int tx = threadIdx.x, ty = threadIdx.y;
#pragma unroll
    for (int i = 0; i < 4; ++i)
        t[ty + i * 8][tx] = W[(size_t)(k0 + ty + i * 8) * N + n0 + tx];
    __syncthreads();
#pragma unroll
    for (int i = 0; i < 4; ++i) {
        int r = ty + i * 8;
        float v = t[tx][r];
        __half h = __float2half_rn(v);
        __half l = __float2half_rn(v - __half2float(h));
        Th[(size_t)(n0 + r) * K + k0 + tx] = h;
        Tl[(size_t)(n0 + r) * K + k0 + tx] = l;
    }
}

// -------- depthwise causal conv (K=4) + bias + SiLU; also silu(z) --------
__global__ void conv_silu_kernel(const float* __restrict__ conv_w,
                                 const float* __restrict__ conv_b)
{
    const int m = blockIdx.x;
    const int b = m / LSEQ;
    const int l = m % LSEQ;
    for (int c = threadIdx.x; c < DINNER; c += blockDim.x) {
        float s = conv_b[c];
#pragma unroll
        for (int k = 0; k < KCONV; k++) {
            int ls = l - (KCONV - 1) + k;
            if (ls >= 0)
                s += g_xz[(size_t)(b * LSEQ + ls) * (2 * DINNER) + c] * conv_w[c * KCONV + k];
        }
        g_xs[(size_t)m * DINNER + c] = s / (1.f + __expf(-s));
        float z = g_xz[(size_t)m * (2 * DINNER) + DINNER + c];
        g_sg[(size_t)m * DINNER + c] = z / (1.f + __expf(-z));
    }
}

// ---------------- x-proj split-K partials ----------------
__global__ __launch_bounds__(160) void xp_partial_kernel(const float* __restrict__ W)
{
    __shared__ float s[16][KSZ];
    const int m0 = blockIdx.x * 16;
    const int k0 = blockIdx.y * KSZ;
    const int tid = threadIdx.x;

    for (int idx = tid; idx < 16 * KSZ; idx += blockDim.x) {
        int r = idx / KSZ, k = idx % KSZ;
        s[r][k] = g_xs[(size_t)(m0 + r) * DINNER + k0 + k];
    }
    __syncthreads();

    if (tid < NXP) {
        float acc[16];
#pragma unroll
        for (int r = 0; r < 16; r++) acc[r] = 0.f;
        for (int k = 0; k < KSZ; k++) {
            float w = W[(size_t)(k0 + k) * NXP + tid];
#pragma unroll
            for (int r = 0; r < 16; r++) acc[r] += s[r][k] * w;
        }
#pragma unroll
        for (int r = 0; r < 16; r++)
            g_xpp[(size_t)(blockIdx.y * MROWS + m0 + r) * NXP + tid] = acc[r];
    }
}

__global__ __launch_bounds__(160) void xp_reduce_kernel()
{
    const int m = blockIdx.x;
    const int n = threadIdx.x;
    if (n >= NXP) return;
    float sum = 0.f;
#pragma unroll
    for (int kc = 0; kc < KCH; kc++)
        sum += g_xpp[(size_t)(kc * MROWS + m) * NXP + n];
    if (n < DSTATE)            g_Bm[m * DSTATE + n] = sum;
    else if (n < 2 * DSTATE)   g_Cm[m * DSTATE + (n - DSTATE)] = sum;
    else                       g_dtr[m] = sum;
}

// ---------------- dt = softplus(dt_raw * dt_w + dt_b), elementwise ----------
__global__ void dt_pre_kernel(const float* __restrict__ dt_w,
                              const float* __restrict__ dt_b)
{
    const int m = blockIdx.x;
    const float dr = g_dtr[m];
    for (int c = threadIdx.x; c < DINNER; c += blockDim.x) {
        float v = dr * dt_w[c] + dt_b[c];
        g_dtf[(size_t)m * DINNER + c] = (v > 20.f) ? v : log1pf(__expf(v));
    }
}

// ---------------- selective scan: warp-autonomous, 2 MUFU per t -------------
__global__ __launch_bounds__(256) void scan_kernel(
    const float* __restrict__ A_log, const float* __restrict__ Dp,
    float* __restrict__ state_out)
{
    const int warp = threadIdx.x >> 5;
    const int lane = threadIdx.x & 31;
    const int wg = blockIdx.x * 8 + warp;
    const int b = wg >> 11;
    const int d = wg & (DINNER - 1);

    const float a0 = -__expf(A_log[d * DSTATE + 2 * lane]);
    const float a1 = -__expf(A_log[d * DSTATE + 2 * lane + 1]);
    const float Dd = Dp[d];

    const float2* B2 = (const float2*)g_Bm;
    const float2* C2 = (const float2*)g_Cm;
    const int mbase = b * LSEQ;
    const int mlast = mbase + LSEQ - 1;

    int m = mbase;
    float2 Bn = B2[(size_t)m * 32 + lane];
    float2 Cn = C2[(size_t)m * 32 + lane];
    float dtn = g_dtf[(size_t)m * DINNER + d];
    float xsn = g_xs[(size_t)m * DINNER + d];
    float sgn = g_sg[(size_t)m * DINNER + d];

    float s0 = 0.f, s1 = 0.f;
    for (int t = 0; t < LSEQ; ++t) {
        const float2 Bc = Bn, Cc = Cn;
        const float dtv = dtn, xsc = xsn, sgc = sgn;

        const int mn = (m < mlast) ? m + 1 : mlast;
        Bn  = B2[(size_t)mn * 32 + lane];
        Cn  = C2[(size_t)mn * 32 + lane];
        dtn = g_dtf[(size_t)mn * DINNER + d];
        xsn = g_xs[(size_t)mn * DINNER + d];
        sgn = g_sg[(size_t)mn * DINNER + d];

        const float dx = dtv * xsc;
        s0 = __expf(dtv * a0) * s0 + dx * Bc.x;
        s1 = __expf(dtv * a1) * s1 + dx * Bc.y;

        float acc = s0 * Cc.x + s1 * Cc.y;
#pragma unroll
        for (int o = 16; o; o >>= 1) acc += __shfl_xor_sync(0xffffffffu, acc, o);

        if (lane == 0) {
            const float yv = (acc + Dd * xsc) * sgc;
            g_yh[(size_t)m * DINNER + d] = __float2half_rn(yv);
        }
        m++;
    }
    ((float2*)state_out)[(size_t)(b * DINNER + d) * 32 + lane] = make_float2(s0, s1);
}

// ---------------- launch ----------------
extern "C" void kernel_launch(void* const* d_in, const int* in_sizes, int n_in,
                              void* d_out, int out_size)
{
    const float* x          = (const float*)d_in[0];
    const float* in_proj_w  = (const float*)d_in[1];
    const float* conv_w     = (const float*)d_in[2];
    const float* conv_b     = (const float*)d_in[3];
    const float* x_proj_w   = (const float*)d_in[4];
    const float* dt_w       = (const float*)d_in[5];
    const float* dt_b       = (const float*)d_in[6];
    const float* A_log      = (const float*)d_in[7];
    const float* Dp         = (const float*)d_in[8];
    const float* out_proj_w = (const float*)d_in[9];
    float* out = (float*)d_out;

    void* p;
    cudaGetSymbolAddress(&p, g_xz);  float*  p_xz  = (float*)p;
    cudaGetSymbolAddress(&p, g_xh);  __half* p_xh  = (__half*)p;
    cudaGetSymbolAddress(&p, g_w1h); __half* p_w1h = (__half*)p;
    cudaGetSymbolAddress(&p, g_w1l); __half* p_w1l = (__half*)p;
    cudaGetSymbolAddress(&p, g_w3h); __half* p_w3h = (__half*)p;
    cudaGetSymbolAddress(&p, g_w3l); __half* p_w3l = (__half*)p;
    cudaGetSymbolAddress(&p, g_yh);  __half* p_yh  = (__half*)p;

    cudaFuncSetAttribute(gemm_a16, cudaFuncAttributeMaxDynamicSharedMemorySize, GSMEM);

    cudaMemsetAsync(out, 0, (size_t)OUT_ELEMS * sizeof(float));

    // 0) pre-passes
    cvt_x_kernel<<<(MROWS * DMODEL) / 1024, 256>>>(x);
    tconv_kernel<<<dim3(2 * DINNER / 32, DMODEL / 32), dim3(32, 8)>>>(
        in_proj_w, p_w1h, p_w1l, DMODEL, 2 * DINNER);
    tconv_kernel<<<dim3(DMODEL / 32, DINNER / 32), dim3(32, 8)>>>(
        out_proj_w, p_w3h, p_w3l, DINNER, DMODEL);

    // 1) xz = x @ in_proj_w
    gemm_a16<<<dim3(2 * DINNER / BN, MROWS / BM, 1), 256, GSMEM>>>(
        p_xh, p_w1h, p_w1l, p_xz, MROWS, 2 * DINNER, DMODEL, 1);

    // 2) conv + SiLU (+ silu(z))
    conv_silu_kernel<<<MROWS, 256>>>(conv_w, conv_b);

    // 3) x-proj
    xp_partial_kernel<<<dim3(MROWS / 16, KCH), 160>>>(x_proj_w);
    xp_reduce_kernel<<<MROWS, 160>>>();

    // 3b) dt softplus precompute
    dt_pre_kernel<<<MROWS, 256>>>(dt_w, dt_b);

    // 4) selective scan
    scan_kernel<<<512, 256>>>(A_log, Dp, out + OUT_ELEMS);

    // 5) out = y @ out_proj_w, split-K=4
    gemm_a16<<<dim3(DMODEL / BN, MROWS / BM, 4), 256, GSMEM>>>(
        p_yh, p_w3h, p_w3l, out, MROWS, DMODEL, DINNER, 4);
}